// round 4
// baseline (speedup 1.0000x reference)
#include <cuda_runtime.h>
#include <cuda_bf16.h>

#define N_NODES 100000
#define N_EDGES 1600000
#define N_FEAT  16
#define HIDDEN  128
#define N_GRAPHS 512
#define HV4 (HIDDEN / 4)          // 32 float4 per node row
#define SCAN_B 1024
#define NB ((N_NODES + SCAN_B - 1) / SCAN_B)   // 98

// ---- scratch (device globals; 16B-aligned via float4) ----
__device__ float4 g_h[N_NODES * HV4];     // pre-aggregation features (reused layer1/2)
__device__ float4 g_out[N_NODES * HV4];   // post-aggregation output (reused layer1/2)
__device__ float  g_dinv[N_NODES];
__device__ int    g_deg[N_NODES];
__device__ int    g_cursor[N_NODES];
__device__ int    g_row_start[N_NODES + 1];
__device__ int    g_blocksum[NB];
__device__ int    g_csr_src[N_EDGES];
__device__ int    g_is64;                 // 1 if index inputs are int64, 0 if int32

// Load index i from a buffer that is either int32[] or int64[] (little-endian,
// values < 2^31 so the low word is the value).
__device__ __forceinline__ int idx_at(const int* __restrict__ p, int i, int is64) {
    return is64 ? p[2 * i] : p[i];
}

// ---------------------------------------------------------------------------
// Detect index dtype: edge indices are random in [0, 100000). If the buffer is
// int64, every odd 32-bit word is 0. If int32, that is (1e-5)^32 improbable.
__global__ void detect_kernel(const int* __restrict__ ei_raw) {
    if (threadIdx.x == 0) {
        int allzero = 1;
        for (int i = 1; i < 64; i += 2)
            if (ei_raw[i] != 0) allzero = 0;
        g_is64 = allzero;
    }
}

__global__ void init_kernel() {
    int i = blockIdx.x * blockDim.x + threadIdx.x;
    int stride = gridDim.x * blockDim.x;
    for (int j = i; j < N_NODES; j += stride) { g_deg[j] = 0; g_cursor[j] = 0; }
}

__global__ void deg_kernel(const int* __restrict__ ei_raw) {
    int e = blockIdx.x * blockDim.x + threadIdx.x;
    if (e >= N_EDGES) return;
    int is64 = g_is64;
    const int* dst = ei_raw + (is64 ? 2 * N_EDGES : N_EDGES);
    atomicAdd(&g_deg[idx_at(dst, e, is64)], 1);
}

__global__ void dinv_kernel() {
    int i = blockIdx.x * blockDim.x + threadIdx.x;
    if (i < N_NODES) g_dinv[i] = rsqrtf((float)g_deg[i] + 1.0f);
}

// ---- 3-pass exclusive scan of g_deg -> g_row_start ----
__global__ void blocksum_kernel() {
    __shared__ int wsum[32];
    int b = blockIdx.x;
    int tid = threadIdx.x;
    int i = b * SCAN_B + tid;
    int v = (i < N_NODES) ? g_deg[i] : 0;
#pragma unroll
    for (int off = 16; off; off >>= 1) v += __shfl_down_sync(0xffffffffu, v, off);
    if ((tid & 31) == 0) wsum[tid >> 5] = v;
    __syncthreads();
    if (tid < 32) {
        int s = (tid < SCAN_B / 32) ? wsum[tid] : 0;
#pragma unroll
        for (int off = 16; off; off >>= 1) s += __shfl_down_sync(0xffffffffu, s, off);
        if (tid == 0) g_blocksum[b] = s;
    }
}

__global__ void scanbs_kernel() {
    if (threadIdx.x == 0) {
        int run = 0;
        for (int b = 0; b < NB; b++) { int t = g_blocksum[b]; g_blocksum[b] = run; run += t; }
    }
}

__global__ void rowstart_kernel() {
    __shared__ int sdata[SCAN_B];
    int b = blockIdx.x, tid = threadIdx.x;
    int i = b * SCAN_B + tid;
    int v = (i < N_NODES) ? g_deg[i] : 0;
    sdata[tid] = v;
    __syncthreads();
    for (int off = 1; off < SCAN_B; off <<= 1) {
        int t = (tid >= off) ? sdata[tid - off] : 0;
        __syncthreads();
        sdata[tid] += t;
        __syncthreads();
    }
    int excl = sdata[tid] - v + g_blocksum[b];
    if (i < N_NODES) g_row_start[i] = excl;
    if (i == N_NODES - 1) g_row_start[N_NODES] = excl + v;
}

__global__ void bin_kernel(const int* __restrict__ ei_raw) {
    int e = blockIdx.x * blockDim.x + threadIdx.x;
    if (e >= N_EDGES) return;
    int is64 = g_is64;
    const int* src = ei_raw;
    const int* dst = ei_raw + (is64 ? 2 * N_EDGES : N_EDGES);
    int d = idx_at(dst, e, is64);
    int pos = atomicAdd(&g_cursor[d], 1);
    g_csr_src[g_row_start[d] + pos] = idx_at(src, e, is64);
}

// ---------------------------------------------------------------------------
// Layer 1 GEMM: g_h = x @ W1  (K=16). Warp per node, lane handles 4 cols.
__global__ void gemm1_kernel(const float* __restrict__ x,
                             const float* __restrict__ W1) {
    __shared__ float sW[N_FEAT * HIDDEN];
    int tid = threadIdx.x;
    for (int j = tid; j < N_FEAT * HIDDEN; j += 256) sW[j] = W1[j];
    __syncthreads();

    int node = blockIdx.x * 8 + (tid >> 5);
    int lane = tid & 31;
    if (node >= N_NODES) return;

    const float* xr = x + node * N_FEAT;
    float xv[N_FEAT];
#pragma unroll
    for (int k = 0; k < N_FEAT; k++) xv[k] = __ldg(xr + k);

    int c = lane * 4;
    float4 acc = make_float4(0.f, 0.f, 0.f, 0.f);
#pragma unroll
    for (int k = 0; k < N_FEAT; k++) {
        const float* w = sW + k * HIDDEN + c;
        acc.x += xv[k] * w[0];
        acc.y += xv[k] * w[1];
        acc.z += xv[k] * w[2];
        acc.w += xv[k] * w[3];
    }
    g_h[node * HV4 + lane] = acc;
}

// ---------------------------------------------------------------------------
// CSR gather: g_out[d] = dinv[d]*Σ_s h[s]*dinv[s] + h[d]*dinv[d]^2 + b
// Warp per dst node; unrolled by 2 for MLP.
__global__ void gather_kernel(const float* __restrict__ bias) {
    int w = (blockIdx.x * blockDim.x + threadIdx.x) >> 5;
    int lane = threadIdx.x & 31;
    if (w >= N_NODES) return;

    int beg = g_row_start[w];
    int end = g_row_start[w + 1];
    float4 acc0 = make_float4(0.f, 0.f, 0.f, 0.f);
    float4 acc1 = make_float4(0.f, 0.f, 0.f, 0.f);

    int i = beg;
    for (; i + 1 < end; i += 2) {
        int s0 = g_csr_src[i];
        int s1 = g_csr_src[i + 1];
        float d0 = g_dinv[s0];
        float d1 = g_dinv[s1];
        float4 v0 = g_h[s0 * HV4 + lane];
        float4 v1 = g_h[s1 * HV4 + lane];
        acc0.x += v0.x * d0; acc0.y += v0.y * d0; acc0.z += v0.z * d0; acc0.w += v0.w * d0;
        acc1.x += v1.x * d1; acc1.y += v1.y * d1; acc1.z += v1.z * d1; acc1.w += v1.w * d1;
    }
    if (i < end) {
        int s0 = g_csr_src[i];
        float d0 = g_dinv[s0];
        float4 v0 = g_h[s0 * HV4 + lane];
        acc0.x += v0.x * d0; acc0.y += v0.y * d0; acc0.z += v0.z * d0; acc0.w += v0.w * d0;
    }
    acc0.x += acc1.x; acc0.y += acc1.y; acc0.z += acc1.z; acc0.w += acc1.w;

    float invd = g_dinv[w];
    float d2 = invd * invd;
    float4 hd = g_h[w * HV4 + lane];
    float4 b4 = ((const float4*)bias)[lane];
    g_out[w * HV4 + lane] = make_float4(
        acc0.x * invd + hd.x * d2 + b4.x,
        acc0.y * invd + hd.y * d2 + b4.y,
        acc0.z * invd + hd.z * d2 + b4.z,
        acc0.w * invd + hd.w * d2 + b4.w);
}

// ---------------------------------------------------------------------------
// Layer 2 GEMM: g_h = relu(g_out) @ W2.  BM=64,BN=128,BK=16, 256 thr, 8x4 tile.
__global__ void gemm2_kernel(const float* __restrict__ W2) {
    __shared__ float As[16][64];    // transposed A tile: As[k][m]
    __shared__ float Bs[16][128];

    int tid = threadIdx.x;
    int tx = tid & 31;
    int ty = tid >> 5;

    int row0 = blockIdx.x * 64;
    int arow = tid >> 2;
    int acol0 = (tid & 3) * 4;
    int grow = row0 + arow;
    int brow = tid >> 4;
    int bcol = (tid & 15) * 8;

    float acc[8][4];
#pragma unroll
    for (int i = 0; i < 8; i++)
#pragma unroll
        for (int j = 0; j < 4; j++) acc[i][j] = 0.f;

    for (int kb = 0; kb < HIDDEN; kb += 16) {
        float4 a4 = make_float4(0.f, 0.f, 0.f, 0.f);
        if (grow < N_NODES)
            a4 = g_out[grow * HV4 + (kb >> 2) + (tid & 3)];
        As[acol0 + 0][arow] = fmaxf(a4.x, 0.f);
        As[acol0 + 1][arow] = fmaxf(a4.y, 0.f);
        As[acol0 + 2][arow] = fmaxf(a4.z, 0.f);
        As[acol0 + 3][arow] = fmaxf(a4.w, 0.f);

        float4 bA = *(const float4*)(W2 + (kb + brow) * HIDDEN + bcol);
        float4 bB = *(const float4*)(W2 + (kb + brow) * HIDDEN + bcol + 4);
        *(float4*)&Bs[brow][bcol] = bA;
        *(float4*)&Bs[brow][bcol + 4] = bB;
        __syncthreads();

#pragma unroll
        for (int k = 0; k < 16; k++) {
            float4 bv = *(const float4*)&Bs[k][tx * 4];
            float4 a0 = *(const float4*)&As[k][ty * 8];
            float4 a1 = *(const float4*)&As[k][ty * 8 + 4];
            float a[8] = {a0.x, a0.y, a0.z, a0.w, a1.x, a1.y, a1.z, a1.w};
#pragma unroll
            for (int i = 0; i < 8; i++) {
                acc[i][0] += a[i] * bv.x;
                acc[i][1] += a[i] * bv.y;
                acc[i][2] += a[i] * bv.z;
                acc[i][3] += a[i] * bv.w;
            }
        }
        __syncthreads();
    }

#pragma unroll
    for (int i = 0; i < 8; i++) {
        int row = row0 + ty * 8 + i;
        if (row >= N_NODES) continue;
        g_h[row * HV4 + tx] = make_float4(acc[i][0], acc[i][1], acc[i][2], acc[i][3]);
    }
}

// ---------------------------------------------------------------------------
// Pool + head fused: block per graph (batch sorted). 128 threads, one col each.
__global__ void pool_head_kernel(const int* __restrict__ batch_raw,
                                 const float* __restrict__ Wl,
                                 const float* __restrict__ bl,
                                 float* __restrict__ out) {
    int g = blockIdx.x;
    int tid = threadIdx.x;
    int is64 = g_is64;

    // lower_bound(batch, g) and lower_bound(batch, g+1)
    int lo = 0, hi = N_NODES;
    while (lo < hi) {
        int mid = (lo + hi) >> 1;
        if (idx_at(batch_raw, mid, is64) < g) lo = mid + 1; else hi = mid;
    }
    int beg = lo;
    hi = N_NODES;
    while (lo < hi) {
        int mid = (lo + hi) >> 1;
        if (idx_at(batch_raw, mid, is64) < g + 1) lo = mid + 1; else hi = mid;
    }
    int end = lo;

    const float* outf = (const float*)g_out;
    float acc = 0.f;
    for (int n = beg; n < end; n++)
        acc += fmaxf(outf[n * HIDDEN + tid], 0.f);

    // dot with Wl, block reduce
    float v = acc * __ldg(Wl + tid);
    __shared__ float wsum[4];
#pragma unroll
    for (int off = 16; off; off >>= 1) v += __shfl_down_sync(0xffffffffu, v, off);
    if ((tid & 31) == 0) wsum[tid >> 5] = v;
    __syncthreads();
    if (tid == 0) {
        float tot = wsum[0] + wsum[1] + wsum[2] + wsum[3];
        float cnt = fmaxf((float)(end - beg), 1.0f);
        out[g] = tot / cnt + __ldg(bl);
    }
}

// ---------------------------------------------------------------------------
extern "C" void kernel_launch(void* const* d_in, const int* in_sizes, int n_in,
                              void* d_out, int out_size) {
    const float* x = (const float*)d_in[0];
    const int* ei_raw = (const int*)d_in[1];       // int32 or int64 (auto-detected)
    const int* batch_raw = (const int*)d_in[2];    // same dtype as edge_index
    const float* W1 = (const float*)d_in[3];
    const float* b1 = (const float*)d_in[4];
    const float* W2 = (const float*)d_in[5];
    const float* b2 = (const float*)d_in[6];
    const float* Wl = (const float*)d_in[7];
    const float* bl = (const float*)d_in[8];
    float* out = (float*)d_out;

    detect_kernel<<<1, 32>>>(ei_raw);
    init_kernel<<<256, 256>>>();
    deg_kernel<<<(N_EDGES + 255) / 256, 256>>>(ei_raw);
    dinv_kernel<<<(N_NODES + 255) / 256, 256>>>();

    blocksum_kernel<<<NB, SCAN_B>>>();
    scanbs_kernel<<<1, 32>>>();
    rowstart_kernel<<<NB, SCAN_B>>>();
    bin_kernel<<<(N_EDGES + 255) / 256, 256>>>(ei_raw);

    gemm1_kernel<<<(N_NODES + 7) / 8, 256>>>(x, W1);
    gather_kernel<<<(N_NODES + 7) / 8, 256>>>(b1);

    gemm2_kernel<<<(N_NODES + 63) / 64, 256>>>(W2);
    gather_kernel<<<(N_NODES + 7) / 8, 256>>>(b2);

    pool_head_kernel<<<N_GRAPHS, 128>>>(batch_raw, Wl, bl, out);
}

// round 5
// speedup vs baseline: 1.1942x; 1.1942x over previous
#include <cuda_runtime.h>
#include <cuda_bf16.h>

#define N_NODES 100000
#define N_EDGES 1600000
#define N_FEAT  16
#define HIDDEN  128
#define N_GRAPHS 512
#define HV4 (HIDDEN / 4)          // 32 float4 per node row
#define HU2 (HIDDEN / 4)          // 32 uint2 (4 bf16) per node row
#define SCAN_B 1024
#define NB ((N_NODES + SCAN_B - 1) / SCAN_B)   // 98

// ---- scratch ----
__device__ uint2  g_hb[N_NODES * HU2];    // pre-scaled features h*dinv, bf16 (gather operand)
__device__ float4 g_out[N_NODES * HV4];   // post-aggregation output (fp32)
__device__ float  g_dinv[N_NODES];
__device__ int    g_deg[N_NODES];
__device__ int    g_cursor[N_NODES];
__device__ int    g_row_start[N_NODES + 1];
__device__ int    g_blocksum[NB];
__device__ int    g_csr_src[N_EDGES];
__device__ int    g_is64;

__device__ __forceinline__ int idx_at(const int* __restrict__ p, int i, int is64) {
    return is64 ? p[2 * i] : p[i];
}

// ---- f32x2 packed math helpers ----
__device__ __forceinline__ unsigned long long pack2(float lo, float hi) {
    unsigned long long r;
    asm("mov.b64 %0, {%1, %2};" : "=l"(r) : "f"(lo), "f"(hi));
    return r;
}
__device__ __forceinline__ void fma2(unsigned long long& d, unsigned long long a,
                                     unsigned long long b) {
    asm("fma.rn.f32x2 %0, %1, %2, %3;" : "=l"(d) : "l"(a), "l"(b), "l"(d));
}
__device__ __forceinline__ float2 unpack2(unsigned long long v) {
    float lo, hi;
    asm("mov.b64 {%0, %1}, %2;" : "=f"(lo), "=f"(hi) : "l"(v));
    return make_float2(lo, hi);
}

// pack 4 floats -> 4 bf16 in a uint2
__device__ __forceinline__ uint2 to_bf16x4(float a, float b, float c, float d) {
    __nv_bfloat162 p0 = __float22bfloat162_rn(make_float2(a, b));
    __nv_bfloat162 p1 = __float22bfloat162_rn(make_float2(c, d));
    uint2 u;
    *(__nv_bfloat162*)&u.x = p0;
    *(__nv_bfloat162*)&u.y = p1;
    return u;
}

// ---------------------------------------------------------------------------
__global__ void init_kernel(const int* __restrict__ ei_raw) {
    int i = blockIdx.x * blockDim.x + threadIdx.x;
    int stride = gridDim.x * blockDim.x;
    if (blockIdx.x == 0 && threadIdx.x == 0) {
        // edge indices < 2^31: if buffer is int64, all odd words are 0
        int allzero = 1;
        for (int k = 1; k < 64; k += 2)
            if (ei_raw[k] != 0) allzero = 0;
        g_is64 = allzero;
    }
    for (int j = i; j < N_NODES; j += stride) { g_deg[j] = 0; g_cursor[j] = 0; }
}

__global__ void deg_kernel(const int* __restrict__ ei_raw) {
    int e = blockIdx.x * blockDim.x + threadIdx.x;
    if (e >= N_EDGES) return;
    int is64 = g_is64;
    const int* dst = ei_raw + (is64 ? 2 * N_EDGES : N_EDGES);
    atomicAdd(&g_deg[idx_at(dst, e, is64)], 1);
}

__global__ void dinv_kernel() {
    int i = blockIdx.x * blockDim.x + threadIdx.x;
    if (i < N_NODES) g_dinv[i] = rsqrtf((float)g_deg[i] + 1.0f);
}

// ---- 3-pass exclusive scan of g_deg -> g_row_start ----
__global__ void blocksum_kernel() {
    __shared__ int wsum[32];
    int b = blockIdx.x, tid = threadIdx.x;
    int i = b * SCAN_B + tid;
    int v = (i < N_NODES) ? g_deg[i] : 0;
#pragma unroll
    for (int off = 16; off; off >>= 1) v += __shfl_down_sync(0xffffffffu, v, off);
    if ((tid & 31) == 0) wsum[tid >> 5] = v;
    __syncthreads();
    if (tid < 32) {
        int s = (tid < SCAN_B / 32) ? wsum[tid] : 0;
#pragma unroll
        for (int off = 16; off; off >>= 1) s += __shfl_down_sync(0xffffffffu, s, off);
        if (tid == 0) g_blocksum[b] = s;
    }
}

__global__ void scanbs_kernel() {
    if (threadIdx.x == 0) {
        int run = 0;
        for (int b = 0; b < NB; b++) { int t = g_blocksum[b]; g_blocksum[b] = run; run += t; }
    }
}

__global__ void rowstart_kernel() {
    __shared__ int sdata[SCAN_B];
    int b = blockIdx.x, tid = threadIdx.x;
    int i = b * SCAN_B + tid;
    int v = (i < N_NODES) ? g_deg[i] : 0;
    sdata[tid] = v;
    __syncthreads();
    for (int off = 1; off < SCAN_B; off <<= 1) {
        int t = (tid >= off) ? sdata[tid - off] : 0;
        __syncthreads();
        sdata[tid] += t;
        __syncthreads();
    }
    int excl = sdata[tid] - v + g_blocksum[b];
    if (i < N_NODES) g_row_start[i] = excl;
    if (i == N_NODES - 1) g_row_start[N_NODES] = excl + v;
}

__global__ void bin_kernel(const int* __restrict__ ei_raw) {
    int e = blockIdx.x * blockDim.x + threadIdx.x;
    if (e >= N_EDGES) return;
    int is64 = g_is64;
    const int* src = ei_raw;
    const int* dst = ei_raw + (is64 ? 2 * N_EDGES : N_EDGES);
    int d = idx_at(dst, e, is64);
    int pos = atomicAdd(&g_cursor[d], 1);
    g_csr_src[g_row_start[d] + pos] = idx_at(src, e, is64);
}

// ---------------------------------------------------------------------------
// Layer 1 GEMM: g_hb = bf16( (x @ W1) * dinv )   (K=16). Warp/node, 4 cols/lane.
__global__ void gemm1_kernel(const float* __restrict__ x,
                             const float* __restrict__ W1) {
    __shared__ float sW[N_FEAT * HIDDEN];
    int tid = threadIdx.x;
    for (int j = tid; j < N_FEAT * HIDDEN; j += 256) sW[j] = W1[j];
    __syncthreads();

    int node = blockIdx.x * 8 + (tid >> 5);
    int lane = tid & 31;
    if (node >= N_NODES) return;

    const float* xr = x + node * N_FEAT;
    float xv[N_FEAT];
#pragma unroll
    for (int k = 0; k < N_FEAT; k++) xv[k] = __ldg(xr + k);

    int c = lane * 4;
    float4 acc = make_float4(0.f, 0.f, 0.f, 0.f);
#pragma unroll
    for (int k = 0; k < N_FEAT; k++) {
        const float* w = sW + k * HIDDEN + c;
        acc.x += xv[k] * w[0];
        acc.y += xv[k] * w[1];
        acc.z += xv[k] * w[2];
        acc.w += xv[k] * w[3];
    }
    float dv = g_dinv[node];
    g_hb[node * HU2 + lane] = to_bf16x4(acc.x * dv, acc.y * dv, acc.z * dv, acc.w * dv);
}

// ---------------------------------------------------------------------------
// CSR gather (bf16 rows, pre-scaled):
//   g_out[d] = dinv[d] * (h_pre[d] + Σ_s h_pre[s]) + bias
// Warp per dst node, lane = 4 cols, unrolled by 4.
__global__ void gather_kernel(const float* __restrict__ bias) {
    int w = (blockIdx.x * blockDim.x + threadIdx.x) >> 5;
    int lane = threadIdx.x & 31;
    if (w >= N_NODES) return;

    int beg = g_row_start[w];
    int end = g_row_start[w + 1];

    float ax = 0.f, ay = 0.f, az = 0.f, aw = 0.f;

    int i = beg;
    for (; i + 3 < end; i += 4) {
        int s0 = g_csr_src[i], s1 = g_csr_src[i + 1];
        int s2 = g_csr_src[i + 2], s3 = g_csr_src[i + 3];
        uint2 u0 = g_hb[s0 * HU2 + lane];
        uint2 u1 = g_hb[s1 * HU2 + lane];
        uint2 u2 = g_hb[s2 * HU2 + lane];
        uint2 u3 = g_hb[s3 * HU2 + lane];
#pragma unroll
        for (int q = 0; q < 4; q++) {
            uint2 u = (q == 0) ? u0 : (q == 1) ? u1 : (q == 2) ? u2 : u3;
            float2 f0 = __bfloat1622float2(*(__nv_bfloat162*)&u.x);
            float2 f1 = __bfloat1622float2(*(__nv_bfloat162*)&u.y);
            ax += f0.x; ay += f0.y; az += f1.x; aw += f1.y;
        }
    }
    for (; i < end; i++) {
        int s0 = g_csr_src[i];
        uint2 u = g_hb[s0 * HU2 + lane];
        float2 f0 = __bfloat1622float2(*(__nv_bfloat162*)&u.x);
        float2 f1 = __bfloat1622float2(*(__nv_bfloat162*)&u.y);
        ax += f0.x; ay += f0.y; az += f1.x; aw += f1.y;
    }

    // self-loop: + h_pre[d]
    {
        uint2 u = g_hb[w * HU2 + lane];
        float2 f0 = __bfloat1622float2(*(__nv_bfloat162*)&u.x);
        float2 f1 = __bfloat1622float2(*(__nv_bfloat162*)&u.y);
        ax += f0.x; ay += f0.y; az += f1.x; aw += f1.y;
    }

    float invd = g_dinv[w];
    float4 b4 = ((const float4*)bias)[lane];
    g_out[w * HV4 + lane] = make_float4(ax * invd + b4.x, ay * invd + b4.y,
                                        az * invd + b4.z, aw * invd + b4.w);
}

// ---------------------------------------------------------------------------
// Layer 2 GEMM: g_hb = bf16( (relu(g_out) @ W2) * dinv ).
// BM=64,BN=128,BK=16, 256 thr, 8x4 register tile using packed fma.rn.f32x2.
__global__ void gemm2_kernel(const float* __restrict__ W2) {
    __shared__ __align__(16) float As[16][64];   // As[k][m]
    __shared__ __align__(16) float Bs[16][128];

    int tid = threadIdx.x;
    int tx = tid & 31;
    int ty = tid >> 5;

    int row0 = blockIdx.x * 64;
    int arow = tid >> 2;
    int acol0 = (tid & 3) * 4;
    int grow = row0 + arow;
    int brow = tid >> 4;
    int bcol = (tid & 15) * 8;

    // acc2[r2][c]: packed pair {row ty*8+2*r2, row ty*8+2*r2+1} for col tx*4+c
    unsigned long long acc2[4][4];
#pragma unroll
    for (int i = 0; i < 4; i++)
#pragma unroll
        for (int j = 0; j < 4; j++) acc2[i][j] = 0ull;

    for (int kb = 0; kb < HIDDEN; kb += 16) {
        float4 a4 = make_float4(0.f, 0.f, 0.f, 0.f);
        if (grow < N_NODES)
            a4 = g_out[grow * HV4 + (kb >> 2) + (tid & 3)];
        As[acol0 + 0][arow] = fmaxf(a4.x, 0.f);
        As[acol0 + 1][arow] = fmaxf(a4.y, 0.f);
        As[acol0 + 2][arow] = fmaxf(a4.z, 0.f);
        As[acol0 + 3][arow] = fmaxf(a4.w, 0.f);

        *(float4*)&Bs[brow][bcol]     = *(const float4*)(W2 + (kb + brow) * HIDDEN + bcol);
        *(float4*)&Bs[brow][bcol + 4] = *(const float4*)(W2 + (kb + brow) * HIDDEN + bcol + 4);
        __syncthreads();

#pragma unroll
        for (int k = 0; k < 16; k++) {
            float4 bv = *(const float4*)&Bs[k][tx * 4];
            unsigned long long b0 = pack2(bv.x, bv.x);
            unsigned long long b1 = pack2(bv.y, bv.y);
            unsigned long long b2 = pack2(bv.z, bv.z);
            unsigned long long b3 = pack2(bv.w, bv.w);
#pragma unroll
            for (int r2 = 0; r2 < 4; r2++) {
                unsigned long long a = *(const unsigned long long*)&As[k][ty * 8 + r2 * 2];
                fma2(acc2[r2][0], a, b0);
                fma2(acc2[r2][1], a, b1);
                fma2(acc2[r2][2], a, b2);
                fma2(acc2[r2][3], a, b3);
            }
        }
        __syncthreads();
    }

#pragma unroll
    for (int r2 = 0; r2 < 4; r2++) {
        float2 c0 = unpack2(acc2[r2][0]);
        float2 c1 = unpack2(acc2[r2][1]);
        float2 c2 = unpack2(acc2[r2][2]);
        float2 c3 = unpack2(acc2[r2][3]);
        int rlo = row0 + ty * 8 + r2 * 2;
        int rhi = rlo + 1;
        if (rlo < N_NODES) {
            float dv = g_dinv[rlo];
            g_hb[rlo * HU2 + tx] = to_bf16x4(c0.x * dv, c1.x * dv, c2.x * dv, c3.x * dv);
        }
        if (rhi < N_NODES) {
            float dv = g_dinv[rhi];
            g_hb[rhi * HU2 + tx] = to_bf16x4(c0.y * dv, c1.y * dv, c2.y * dv, c3.y * dv);
        }
    }
}

// ---------------------------------------------------------------------------
// Pool + head fused: block per graph (batch sorted). 128 threads, one col each.
__global__ void pool_head_kernel(const int* __restrict__ batch_raw,
                                 const float* __restrict__ Wl,
                                 const float* __restrict__ bl,
                                 float* __restrict__ out) {
    int g = blockIdx.x;
    int tid = threadIdx.x;
    int is64 = g_is64;

    int lo = 0, hi = N_NODES;
    while (lo < hi) {
        int mid = (lo + hi) >> 1;
        if (idx_at(batch_raw, mid, is64) < g) lo = mid + 1; else hi = mid;
    }
    int beg = lo;
    hi = N_NODES;
    while (lo < hi) {
        int mid = (lo + hi) >> 1;
        if (idx_at(batch_raw, mid, is64) < g + 1) lo = mid + 1; else hi = mid;
    }
    int end = lo;

    const float* outf = (const float*)g_out;
    float acc = 0.f;
    for (int n = beg; n < end; n++)
        acc += fmaxf(outf[n * HIDDEN + tid], 0.f);

    float v = acc * __ldg(Wl + tid);
    __shared__ float wsum[4];
#pragma unroll
    for (int off = 16; off; off >>= 1) v += __shfl_down_sync(0xffffffffu, v, off);
    if ((tid & 31) == 0) wsum[tid >> 5] = v;
    __syncthreads();
    if (tid == 0) {
        float tot = wsum[0] + wsum[1] + wsum[2] + wsum[3];
        float cnt = fmaxf((float)(end - beg), 1.0f);
        out[g] = tot / cnt + __ldg(bl);
    }
}

// ---------------------------------------------------------------------------
extern "C" void kernel_launch(void* const* d_in, const int* in_sizes, int n_in,
                              void* d_out, int out_size) {
    const float* x = (const float*)d_in[0];
    const int* ei_raw = (const int*)d_in[1];
    const int* batch_raw = (const int*)d_in[2];
    const float* W1 = (const float*)d_in[3];
    const float* b1 = (const float*)d_in[4];
    const float* W2 = (const float*)d_in[5];
    const float* b2 = (const float*)d_in[6];
    const float* Wl = (const float*)d_in[7];
    const float* bl = (const float*)d_in[8];
    float* out = (float*)d_out;

    init_kernel<<<256, 256>>>(ei_raw);
    deg_kernel<<<(N_EDGES + 255) / 256, 256>>>(ei_raw);
    dinv_kernel<<<(N_NODES + 255) / 256, 256>>>();

    blocksum_kernel<<<NB, SCAN_B>>>();
    scanbs_kernel<<<1, 32>>>();
    rowstart_kernel<<<NB, SCAN_B>>>();
    bin_kernel<<<(N_EDGES + 255) / 256, 256>>>(ei_raw);

    gemm1_kernel<<<(N_NODES + 7) / 8, 256>>>(x, W1);
    gather_kernel<<<(N_NODES + 7) / 8, 256>>>(b1);

    gemm2_kernel<<<(N_NODES + 63) / 64, 256>>>(W2);
    gather_kernel<<<(N_NODES + 7) / 8, 256>>>(b2);

    pool_head_kernel<<<N_GRAPHS, 128>>>(batch_raw, Wl, bl, out);
}

// round 7
// speedup vs baseline: 1.5012x; 1.2571x over previous
#include <cuda_runtime.h>
#include <cuda_bf16.h>
#include <cstdint>

#define N_NODES 100000
#define N_EDGES 1600000
#define N_FEAT  16
#define HIDDEN  128
#define N_GRAPHS 512
#define HV4 (HIDDEN / 4)          // 32 float4 per node row (fp32 rows)
#define HU2 (HIDDEN / 4)          // 32 uint2 (4 bf16) per node row
#define SCAN_B 1024
#define NB ((N_NODES + SCAN_B - 1) / SCAN_B)   // 98
#define TILE_M 128
#define GRID2 ((N_NODES + TILE_M - 1) / TILE_M)  // 782
#define PITCH 272                 // smem row pitch (bytes): conflict-free frag loads
#define SM_GEMM2 (2 * 128 * PITCH)  // 69632 dynamic smem

// ---- scratch (uint4/float4 arrays -> 16B alignment) ----
__device__ uint4  g_hb[N_NODES * 16];     // h*dinv, bf16 rows (gather operand / gemm2 out)
__device__ uint4  g_outb[N_NODES * 16];   // relu(out1+b1), bf16 rows (gemm2 A operand)
__device__ float4 g_out[N_NODES * HV4];   // relu(out2+b2), fp32 rows (pool input)
__device__ uint4  g_w2tb[128 * 16];       // W2^T as bf16 [n][k]
__device__ float  g_dinv[N_NODES];
__device__ int    g_deg[N_NODES];
__device__ int    g_cursor[N_NODES];
__device__ int    g_row_start[N_NODES + 1];
__device__ int    g_blocksum[NB];
__device__ int    g_csr_src[N_EDGES];
__device__ int    g_is64;

__device__ __forceinline__ int idx_at(const int* __restrict__ p, int i, int is64) {
    return is64 ? p[2 * i] : p[i];
}

__device__ __forceinline__ uint2 to_bf16x4(float a, float b, float c, float d) {
    __nv_bfloat162 p0 = __float22bfloat162_rn(make_float2(a, b));
    __nv_bfloat162 p1 = __float22bfloat162_rn(make_float2(c, d));
    uint2 u;
    *(__nv_bfloat162*)&u.x = p0;
    *(__nv_bfloat162*)&u.y = p1;
    return u;
}

__device__ __forceinline__ uint32_t smem_u32(const void* p) {
    uint32_t a;
    asm("{ .reg .u64 t; cvta.to.shared.u64 t, %1; cvt.u32.u64 %0, t; }" : "=r"(a) : "l"(p));
    return a;
}

// ---------------------------------------------------------------------------
__global__ void init_kernel(const int* __restrict__ ei_raw) {
    int i = blockIdx.x * blockDim.x + threadIdx.x;
    int stride = gridDim.x * blockDim.x;
    if (blockIdx.x == 0 && threadIdx.x == 0) {
        int allzero = 1;
        for (int k = 1; k < 64; k += 2)
            if (ei_raw[k] != 0) allzero = 0;
        g_is64 = allzero;
    }
    for (int j = i; j < N_NODES; j += stride) { g_deg[j] = 0; g_cursor[j] = 0; }
}

__global__ void deg_kernel(const int* __restrict__ ei_raw) {
    int e = blockIdx.x * blockDim.x + threadIdx.x;
    if (e >= N_EDGES) return;
    int is64 = g_is64;
    const int* dst = ei_raw + (is64 ? 2 * N_EDGES : N_EDGES);
    atomicAdd(&g_deg[idx_at(dst, e, is64)], 1);
}

__global__ void blocksum_kernel() {
    __shared__ int wsum[32];
    int b = blockIdx.x, tid = threadIdx.x;
    int i = b * SCAN_B + tid;
    int v = (i < N_NODES) ? g_deg[i] : 0;
#pragma unroll
    for (int off = 16; off; off >>= 1) v += __shfl_down_sync(0xffffffffu, v, off);
    if ((tid & 31) == 0) wsum[tid >> 5] = v;
    __syncthreads();
    if (tid < 32) {
        int s = (tid < SCAN_B / 32) ? wsum[tid] : 0;
#pragma unroll
        for (int off = 16; off; off >>= 1) s += __shfl_down_sync(0xffffffffu, s, off);
        if (tid == 0) g_blocksum[b] = s;
    }
}

__global__ void scanbs_kernel() {
    if (threadIdx.x == 0) {
        int run = 0;
        for (int b = 0; b < NB; b++) { int t = g_blocksum[b]; g_blocksum[b] = run; run += t; }
    }
}

// rowstart scan + dinv fused
__global__ void rowstart_kernel() {
    __shared__ int sdata[SCAN_B];
    int b = blockIdx.x, tid = threadIdx.x;
    int i = b * SCAN_B + tid;
    int v = (i < N_NODES) ? g_deg[i] : 0;
    if (i < N_NODES) g_dinv[i] = rsqrtf((float)v + 1.0f);
    sdata[tid] = v;
    __syncthreads();
    for (int off = 1; off < SCAN_B; off <<= 1) {
        int t = (tid >= off) ? sdata[tid - off] : 0;
        __syncthreads();
        sdata[tid] += t;
        __syncthreads();
    }
    int excl = sdata[tid] - v + g_blocksum[b];
    if (i < N_NODES) g_row_start[i] = excl;
    if (i == N_NODES - 1) g_row_start[N_NODES] = excl + v;
}

__global__ void bin_kernel(const int* __restrict__ ei_raw) {
    int e = blockIdx.x * blockDim.x + threadIdx.x;
    if (e >= N_EDGES) return;
    int is64 = g_is64;
    const int* src = ei_raw;
    const int* dst = ei_raw + (is64 ? 2 * N_EDGES : N_EDGES);
    int d = idx_at(dst, e, is64);
    int pos = atomicAdd(&g_cursor[d], 1);
    g_csr_src[g_row_start[d] + pos] = idx_at(src, e, is64);
}

// ---------------------------------------------------------------------------
// W2 -> W2tb[n][k] bf16 (transposed: B operand, k contiguous)
__global__ void w2cvt_kernel(const float* __restrict__ W2) {
    int t = blockIdx.x * 256 + threadIdx.x;
    if (t >= 128 * 16) return;
    int n = t >> 4, ch = t & 15;
    int k0 = ch * 8;
    uint32_t w[4];
#pragma unroll
    for (int j = 0; j < 4; j++) {
        float lo = W2[(k0 + 2 * j) * HIDDEN + n];
        float hi = W2[(k0 + 2 * j + 1) * HIDDEN + n];
        asm("cvt.rn.bf16x2.f32 %0, %1, %2;" : "=r"(w[j]) : "f"(hi), "f"(lo));
    }
    g_w2tb[t] = make_uint4(w[0], w[1], w[2], w[3]);
}

// Layer 1 GEMM: g_hb = bf16( (x @ W1) * dinv )   (K=16). Warp/node, 4 cols/lane.
__global__ void gemm1_kernel(const float* __restrict__ x,
                             const float* __restrict__ W1) {
    __shared__ float sW[N_FEAT * HIDDEN];
    int tid = threadIdx.x;
    for (int j = tid; j < N_FEAT * HIDDEN; j += 256) sW[j] = W1[j];
    __syncthreads();

    int node = blockIdx.x * 8 + (tid >> 5);
    int lane = tid & 31;
    if (node >= N_NODES) return;

    const float* xr = x + node * N_FEAT;
    float xv[N_FEAT];
#pragma unroll
    for (int k = 0; k < N_FEAT; k++) xv[k] = __ldg(xr + k);

    int c = lane * 4;
    float4 acc = make_float4(0.f, 0.f, 0.f, 0.f);
#pragma unroll
    for (int k = 0; k < N_FEAT; k++) {
        const float* w = sW + k * HIDDEN + c;
        acc.x += xv[k] * w[0];
        acc.y += xv[k] * w[1];
        acc.z += xv[k] * w[2];
        acc.w += xv[k] * w[3];
    }
    float dv = g_dinv[node];
    ((uint2*)g_hb)[node * HU2 + lane] =
        to_bf16x4(acc.x * dv, acc.y * dv, acc.z * dv, acc.w * dv);
}

// ---------------------------------------------------------------------------
// CSR gather: v = dinv[d]*(h_pre[d] + Σ_s h_pre[s]) + bias;  out = relu(v)
// mode 0: write bf16 g_outb   mode 1: write fp32 g_out
__global__ void gather_kernel(const float* __restrict__ bias, int mode) {
    int w = (blockIdx.x * blockDim.x + threadIdx.x) >> 5;
    int lane = threadIdx.x & 31;
    if (w >= N_NODES) return;

    int beg = g_row_start[w];
    int end = g_row_start[w + 1];

    float ax = 0.f, ay = 0.f, az = 0.f, aw = 0.f;
    const uint2* hb = (const uint2*)g_hb;

    int i = beg;
    for (; i + 3 < end; i += 4) {
        int s0 = g_csr_src[i], s1 = g_csr_src[i + 1];
        int s2 = g_csr_src[i + 2], s3 = g_csr_src[i + 3];
        uint2 u0 = hb[s0 * HU2 + lane];
        uint2 u1 = hb[s1 * HU2 + lane];
        uint2 u2 = hb[s2 * HU2 + lane];
        uint2 u3 = hb[s3 * HU2 + lane];
#pragma unroll
        for (int q = 0; q < 4; q++) {
            uint2 u = (q == 0) ? u0 : (q == 1) ? u1 : (q == 2) ? u2 : u3;
            float2 f0 = __bfloat1622float2(*(__nv_bfloat162*)&u.x);
            float2 f1 = __bfloat1622float2(*(__nv_bfloat162*)&u.y);
            ax += f0.x; ay += f0.y; az += f1.x; aw += f1.y;
        }
    }
    for (; i < end; i++) {
        uint2 u = hb[g_csr_src[i] * HU2 + lane];
        float2 f0 = __bfloat1622float2(*(__nv_bfloat162*)&u.x);
        float2 f1 = __bfloat1622float2(*(__nv_bfloat162*)&u.y);
        ax += f0.x; ay += f0.y; az += f1.x; aw += f1.y;
    }
    {   // self loop
        uint2 u = hb[w * HU2 + lane];
        float2 f0 = __bfloat1622float2(*(__nv_bfloat162*)&u.x);
        float2 f1 = __bfloat1622float2(*(__nv_bfloat162*)&u.y);
        ax += f0.x; ay += f0.y; az += f1.x; aw += f1.y;
    }

    float invd = g_dinv[w];
    float4 b4 = ((const float4*)bias)[lane];
    float vx = fmaxf(ax * invd + b4.x, 0.f);
    float vy = fmaxf(ay * invd + b4.y, 0.f);
    float vz = fmaxf(az * invd + b4.z, 0.f);
    float vw = fmaxf(aw * invd + b4.w, 0.f);
    if (mode == 0)
        ((uint2*)g_outb)[w * HU2 + lane] = to_bf16x4(vx, vy, vz, vw);
    else
        g_out[w * HV4 + lane] = make_float4(vx, vy, vz, vw);
}

// ---------------------------------------------------------------------------
// Layer 2 GEMM via mma.sync (HMMA, base PTX): g_hb = bf16((g_outb @ W2) * dinv)
// CTA: 128 rows x N=128 x K=128. 8 warps; warp = m16 x n128 (16 frags).
__global__ __launch_bounds__(256) void gemm2_hmma_kernel() {
    extern __shared__ __align__(16) uint8_t smem[];
    uint8_t* sA = smem;                  // 128 x PITCH
    uint8_t* sB = smem + 128 * PITCH;    // 128 x PITCH (row n, k contiguous)

    int tid = threadIdx.x, wid = tid >> 5, lane = tid & 31;
    int row0 = blockIdx.x * TILE_M;

    const uint4 zero4 = make_uint4(0, 0, 0, 0);
    for (int g = tid; g < 2048; g += 256) {
        int row = g >> 4, ch = g & 15;
        uint4 va = (row0 + row < N_NODES) ? g_outb[(row0 + row) * 16 + ch] : zero4;
        *(uint4*)(sA + row * PITCH + ch * 16) = va;
        *(uint4*)(sB + row * PITCH + ch * 16) = g_w2tb[g];
    }
    __syncthreads();

    float acc[16][4];
#pragma unroll
    for (int f = 0; f < 16; f++)
#pragma unroll
        for (int j = 0; j < 4; j++) acc[f][j] = 0.f;

    int r = lane >> 2;            // row-in-8 / n-in-8
    int kc2 = (lane & 3) * 4;     // byte offset of k-pair ((lane&3)*2 bf16)
    uint32_t aAddr = smem_u32(sA) + (wid * 16 + r) * PITCH + kc2;
    uint32_t bAddr = smem_u32(sB) + r * PITCH + kc2;

#pragma unroll
    for (int ks = 0; ks < 8; ks++) {
        uint32_t a0, a1, a2, a3;
        uint32_t ka = aAddr + ks * 32;   // k0*2 bytes
        asm volatile("ld.shared.b32 %0,[%1];" : "=r"(a0) : "r"(ka));
        asm volatile("ld.shared.b32 %0,[%1];" : "=r"(a1) : "r"(ka + 8 * PITCH));
        asm volatile("ld.shared.b32 %0,[%1];" : "=r"(a2) : "r"(ka + 16));
        asm volatile("ld.shared.b32 %0,[%1];" : "=r"(a3) : "r"(ka + 8 * PITCH + 16));
#pragma unroll
        for (int f = 0; f < 16; f++) {
            uint32_t b0, b1;
            uint32_t kb = bAddr + ks * 32 + f * 8 * PITCH;
            asm volatile("ld.shared.b32 %0,[%1];" : "=r"(b0) : "r"(kb));
            asm volatile("ld.shared.b32 %0,[%1];" : "=r"(b1) : "r"(kb + 16));
            asm volatile(
                "mma.sync.aligned.m16n8k16.row.col.f32.bf16.bf16.f32 "
                "{%0,%1,%2,%3},{%4,%5,%6,%7},{%8,%9},{%0,%1,%2,%3};"
                : "+f"(acc[f][0]), "+f"(acc[f][1]), "+f"(acc[f][2]), "+f"(acc[f][3])
                : "r"(a0), "r"(a1), "r"(a2), "r"(a3), "r"(b0), "r"(b1));
        }
    }

    // Epilogue: scale by dinv, pack bf16x2, store to g_hb
    int rlo = row0 + wid * 16 + r;
    int rhi = rlo + 8;
    float dlo = (rlo < N_NODES) ? g_dinv[rlo] : 0.f;
    float dhi = (rhi < N_NODES) ? g_dinv[rhi] : 0.f;
    uint32_t* ghw = (uint32_t*)g_hb;
    int wcol = (lane & 3);            // word index within frag (c = 2*wcol)
#pragma unroll
    for (int f = 0; f < 16; f++) {
        uint32_t plo, phi;
        asm("cvt.rn.bf16x2.f32 %0, %1, %2;" : "=r"(plo)
            : "f"(acc[f][1] * dlo), "f"(acc[f][0] * dlo));
        asm("cvt.rn.bf16x2.f32 %0, %1, %2;" : "=r"(phi)
            : "f"(acc[f][3] * dhi), "f"(acc[f][2] * dhi));
        if (rlo < N_NODES) ghw[rlo * 64 + f * 4 + wcol] = plo;
        if (rhi < N_NODES) ghw[rhi * 64 + f * 4 + wcol] = phi;
    }
}

// ---------------------------------------------------------------------------
// Pool + head fused: block per graph (batch sorted; relu already applied).
__global__ void pool_head_kernel(const int* __restrict__ batch_raw,
                                 const float* __restrict__ Wl,
                                 const float* __restrict__ bl,
                                 float* __restrict__ out) {
    int g = blockIdx.x;
    int tid = threadIdx.x;
    int is64 = g_is64;

    int lo = 0, hi = N_NODES;
    while (lo < hi) {
        int mid = (lo + hi) >> 1;
        if (idx_at(batch_raw, mid, is64) < g) lo = mid + 1; else hi = mid;
    }
    int beg = lo;
    hi = N_NODES;
    while (lo < hi) {
        int mid = (lo + hi) >> 1;
        if (idx_at(batch_raw, mid, is64) < g + 1) lo = mid + 1; else hi = mid;
    }
    int end = lo;

    const float* outf = (const float*)g_out;
    float acc = 0.f;
    for (int n = beg; n < end; n++)
        acc += outf[n * HIDDEN + tid];

    float v = acc * __ldg(Wl + tid);
    __shared__ float wsum[4];
#pragma unroll
    for (int off = 16; off; off >>= 1) v += __shfl_down_sync(0xffffffffu, v, off);
    if ((tid & 31) == 0) wsum[tid >> 5] = v;
    __syncthreads();
    if (tid == 0) {
        float tot = wsum[0] + wsum[1] + wsum[2] + wsum[3];
        float cnt = fmaxf((float)(end - beg), 1.0f);
        out[g] = tot / cnt + __ldg(bl);
    }
}

// ---------------------------------------------------------------------------
extern "C" void kernel_launch(void* const* d_in, const int* in_sizes, int n_in,
                              void* d_out, int out_size) {
    const float* x = (const float*)d_in[0];
    const int* ei_raw = (const int*)d_in[1];
    const int* batch_raw = (const int*)d_in[2];
    const float* W1 = (const float*)d_in[3];
    const float* b1 = (const float*)d_in[4];
    const float* W2 = (const float*)d_in[5];
    const float* b2 = (const float*)d_in[6];
    const float* Wl = (const float*)d_in[7];
    const float* bl = (const float*)d_in[8];
    float* out = (float*)d_out;

    cudaFuncSetAttribute(gemm2_hmma_kernel,
                         cudaFuncAttributeMaxDynamicSharedMemorySize, SM_GEMM2);

    init_kernel<<<256, 256>>>(ei_raw);
    deg_kernel<<<(N_EDGES + 255) / 256, 256>>>(ei_raw);

    blocksum_kernel<<<NB, SCAN_B>>>();
    scanbs_kernel<<<1, 32>>>();
    rowstart_kernel<<<NB, SCAN_B>>>();
    bin_kernel<<<(N_EDGES + 255) / 256, 256>>>(ei_raw);

    w2cvt_kernel<<<8, 256>>>(W2);
    gemm1_kernel<<<(N_NODES + 7) / 8, 256>>>(x, W1);
    gather_kernel<<<(N_NODES + 7) / 8, 256>>>(b1, 0);

    gemm2_hmma_kernel<<<GRID2, 256, SM_GEMM2>>>();
    gather_kernel<<<(N_NODES + 7) / 8, 256>>>(b2, 1);

    pool_head_kernel<<<N_GRAPHS, 128>>>(batch_raw, Wl, bl, out);
}

// round 8
// speedup vs baseline: 1.5346x; 1.0222x over previous
#include <cuda_runtime.h>
#include <cuda_bf16.h>
#include <cstdint>

#define N_NODES 100000
#define N_EDGES 1600000
#define N_FEAT  16
#define HIDDEN  128
#define N_GRAPHS 512
#define HU2 (HIDDEN / 4)          // 32 uint2 (4 bf16) per node row
#define SCAN_B 1024
#define NB ((N_NODES + SCAN_B - 1) / SCAN_B)   // 98
#define TILE_M 128
#define GRID2 ((N_NODES + TILE_M - 1) / TILE_M)  // 782
#define PITCH 272                 // smem row pitch (bytes): conflict-free frag loads
#define SM_GEMM2 (2 * 128 * PITCH)  // 69632 dynamic smem

// ---- scratch ----
__device__ uint4  g_hb[N_NODES * 16];     // h*dinv, bf16 rows (gather in / gemm out)
__device__ uint4  g_outb[N_NODES * 16];   // relu(out+b), bf16 rows (gemm2 A / pool in)
__device__ uint4  g_w2tb[128 * 16];       // W2^T as bf16 [n][k]
__device__ float  g_dinv[N_NODES];
__device__ int    g_deg[N_NODES];
__device__ int    g_cursor[N_NODES];
__device__ int    g_row_start[N_NODES + 1];
__device__ int    g_blocksum[NB];
__device__ int    g_csr_src[N_EDGES];
__device__ int    g_is64;

__device__ __forceinline__ int idx_at(const int* __restrict__ p, int i, int is64) {
    return is64 ? p[2 * i] : p[i];
}

__device__ __forceinline__ uint32_t smem_u32(const void* p) {
    uint32_t a;
    asm("{ .reg .u64 t; cvta.to.shared.u64 t, %1; cvt.u32.u64 %0, t; }" : "=r"(a) : "l"(p));
    return a;
}

// ---------------------------------------------------------------------------
// W2 -> W2tb[n][k] bf16 (transposed) + index-dtype detection (block 0)
__global__ void w2cvt_kernel(const float* __restrict__ W2,
                             const int* __restrict__ ei_raw) {
    if (blockIdx.x == 0 && threadIdx.x == 0) {
        // indices < 2^31: if buffer is int64, all odd 32-bit words are 0
        int allzero = 1;
        for (int k = 1; k < 64; k += 2)
            if (ei_raw[k] != 0) allzero = 0;
        g_is64 = allzero;
    }
    int t = blockIdx.x * 256 + threadIdx.x;
    if (t >= 128 * 16) return;
    int n = t >> 4, ch = t & 15;
    int k0 = ch * 8;
    uint32_t w[4];
#pragma unroll
    for (int j = 0; j < 4; j++) {
        float lo = W2[(k0 + 2 * j) * HIDDEN + n];
        float hi = W2[(k0 + 2 * j + 1) * HIDDEN + n];
        asm("cvt.rn.bf16x2.f32 %0, %1, %2;" : "=r"(w[j]) : "f"(hi), "f"(lo));
    }
    g_w2tb[t] = make_uint4(w[0], w[1], w[2], w[3]);
}

__global__ void deg_kernel(const int* __restrict__ ei_raw) {
    int e = blockIdx.x * blockDim.x + threadIdx.x;
    if (e >= N_EDGES) return;
    int is64 = g_is64;
    const int* dst = ei_raw + (is64 ? 2 * N_EDGES : N_EDGES);
    atomicAdd(&g_deg[idx_at(dst, e, is64)], 1);
}

__global__ void blocksum_kernel() {
    __shared__ int wsum[32];
    int b = blockIdx.x, tid = threadIdx.x;
    int i = b * SCAN_B + tid;
    int v = (i < N_NODES) ? g_deg[i] : 0;
#pragma unroll
    for (int off = 16; off; off >>= 1) v += __shfl_down_sync(0xffffffffu, v, off);
    if ((tid & 31) == 0) wsum[tid >> 5] = v;
    __syncthreads();
    if (tid < 32) {
        int s = (tid < SCAN_B / 32) ? wsum[tid] : 0;
#pragma unroll
        for (int off = 16; off; off >>= 1) s += __shfl_down_sync(0xffffffffu, s, off);
        if (tid == 0) g_blocksum[b] = s;
    }
}

// rowstart scan (with per-block inline prefix of blocksums) + dinv, fused
__global__ void rowstart_kernel() {
    __shared__ int sdata[SCAN_B];
    __shared__ int s_pref;
    int b = blockIdx.x, tid = threadIdx.x;

    if (tid < 32) {                       // prefix of blocksum[0..b)
        int sum = 0;
        for (int j = tid; j < b; j += 32) sum += g_blocksum[j];
#pragma unroll
        for (int off = 16; off; off >>= 1) sum += __shfl_down_sync(0xffffffffu, sum, off);
        if (tid == 0) s_pref = sum;
    }

    int i = b * SCAN_B + tid;
    int v = (i < N_NODES) ? g_deg[i] : 0;
    if (i < N_NODES) g_dinv[i] = rsqrtf((float)v + 1.0f);
    sdata[tid] = v;
    __syncthreads();
    for (int off = 1; off < SCAN_B; off <<= 1) {
        int t = (tid >= off) ? sdata[tid - off] : 0;
        __syncthreads();
        sdata[tid] += t;
        __syncthreads();
    }
    int excl = sdata[tid] - v + s_pref;
    if (i < N_NODES) g_row_start[i] = excl;
    if (i == N_NODES - 1) g_row_start[N_NODES] = excl + v;
}

__global__ void bin_kernel(const int* __restrict__ ei_raw) {
    int e = blockIdx.x * blockDim.x + threadIdx.x;
    if (e >= N_EDGES) return;
    int is64 = g_is64;
    const int* src = ei_raw;
    const int* dst = ei_raw + (is64 ? 2 * N_EDGES : N_EDGES);
    int d = idx_at(dst, e, is64);
    int pos = atomicAdd(&g_cursor[d], 1);
    g_csr_src[g_row_start[d] + pos] = idx_at(src, e, is64);
}

// ---------------------------------------------------------------------------
// Layer 1 GEMM: g_hb = bf16( (x @ W1) * dinv )   (K=16). Warp/node, 4 cols/lane.
__global__ void gemm1_kernel(const float* __restrict__ x,
                             const float* __restrict__ W1) {
    __shared__ float sW[N_FEAT * HIDDEN];
    int tid = threadIdx.x;
    for (int j = tid; j < N_FEAT * HIDDEN; j += 256) sW[j] = W1[j];
    __syncthreads();

    int node = blockIdx.x * 8 + (tid >> 5);
    int lane = tid & 31;
    if (node >= N_NODES) return;

    const float* xr = x + node * N_FEAT;
    float xv[N_FEAT];
#pragma unroll
    for (int k = 0; k < N_FEAT; k++) xv[k] = __ldg(xr + k);

    int c = lane * 4;
    float4 acc = make_float4(0.f, 0.f, 0.f, 0.f);
#pragma unroll
    for (int k = 0; k < N_FEAT; k++) {
        const float* w = sW + k * HIDDEN + c;
        acc.x += xv[k] * w[0];
        acc.y += xv[k] * w[1];
        acc.z += xv[k] * w[2];
        acc.w += xv[k] * w[3];
    }
    float dv = g_dinv[node];
    __nv_bfloat162 p0 = __float22bfloat162_rn(make_float2(acc.x * dv, acc.y * dv));
    __nv_bfloat162 p1 = __float22bfloat162_rn(make_float2(acc.z * dv, acc.w * dv));
    uint2 u;
    *(__nv_bfloat162*)&u.x = p0;
    *(__nv_bfloat162*)&u.y = p1;
    ((uint2*)g_hb)[node * HU2 + lane] = u;
}

// ---------------------------------------------------------------------------
// CSR gather: v = dinv[d]*(h_pre[d] + Σ_s h_pre[s]) + bias;  g_outb = bf16(relu(v))
// Warp per dst node; half-warp per edge, uint4 (8 bf16) per lane.
__global__ void gather_kernel(const float* __restrict__ bias) {
    int w = (blockIdx.x * blockDim.x + threadIdx.x) >> 5;
    int lane = threadIdx.x & 31;
    if (w >= N_NODES) return;

    int beg = g_row_start[w];
    int end = g_row_start[w + 1];
    int half = lane >> 4;       // which edge of the pair
    int l16 = lane & 15;        // 8-col chunk index

    float a0 = 0.f, a1 = 0.f, a2 = 0.f, a3 = 0.f;
    float a4 = 0.f, a5 = 0.f, a6 = 0.f, a7 = 0.f;

    int i = beg;
    for (; i + 1 < end; i += 2) {
        int s = g_csr_src[i + half];
        uint4 v = g_hb[s * 16 + l16];
        float2 f0 = __bfloat1622float2(*(__nv_bfloat162*)&v.x);
        float2 f1 = __bfloat1622float2(*(__nv_bfloat162*)&v.y);
        float2 f2 = __bfloat1622float2(*(__nv_bfloat162*)&v.z);
        float2 f3 = __bfloat1622float2(*(__nv_bfloat162*)&v.w);
        a0 += f0.x; a1 += f0.y; a2 += f1.x; a3 += f1.y;
        a4 += f2.x; a5 += f2.y; a6 += f3.x; a7 += f3.y;
    }
    if (i < end && half == 0) {     // odd tail: half 0 only
        int s = g_csr_src[i];
        uint4 v = g_hb[s * 16 + l16];
        float2 f0 = __bfloat1622float2(*(__nv_bfloat162*)&v.x);
        float2 f1 = __bfloat1622float2(*(__nv_bfloat162*)&v.y);
        float2 f2 = __bfloat1622float2(*(__nv_bfloat162*)&v.z);
        float2 f3 = __bfloat1622float2(*(__nv_bfloat162*)&v.w);
        a0 += f0.x; a1 += f0.y; a2 += f1.x; a3 += f1.y;
        a4 += f2.x; a5 += f2.y; a6 += f3.x; a7 += f3.y;
    }

    // combine the two halves (lane l and l^16 hold same columns)
    a0 += __shfl_xor_sync(0xffffffffu, a0, 16);
    a1 += __shfl_xor_sync(0xffffffffu, a1, 16);
    a2 += __shfl_xor_sync(0xffffffffu, a2, 16);
    a3 += __shfl_xor_sync(0xffffffffu, a3, 16);
    a4 += __shfl_xor_sync(0xffffffffu, a4, 16);
    a5 += __shfl_xor_sync(0xffffffffu, a5, 16);
    a6 += __shfl_xor_sync(0xffffffffu, a6, 16);
    a7 += __shfl_xor_sync(0xffffffffu, a7, 16);

    if (half == 0) {
        // self loop
        uint4 v = g_hb[w * 16 + l16];
        float2 f0 = __bfloat1622float2(*(__nv_bfloat162*)&v.x);
        float2 f1 = __bfloat1622float2(*(__nv_bfloat162*)&v.y);
        float2 f2 = __bfloat1622float2(*(__nv_bfloat162*)&v.z);
        float2 f3 = __bfloat1622float2(*(__nv_bfloat162*)&v.w);
        a0 += f0.x; a1 += f0.y; a2 += f1.x; a3 += f1.y;
        a4 += f2.x; a5 += f2.y; a6 += f3.x; a7 += f3.y;

        float invd = g_dinv[w];
        float4 b0 = ((const float4*)bias)[l16 * 2];
        float4 b1 = ((const float4*)bias)[l16 * 2 + 1];
        float v0 = fmaxf(a0 * invd + b0.x, 0.f);
        float v1 = fmaxf(a1 * invd + b0.y, 0.f);
        float v2 = fmaxf(a2 * invd + b0.z, 0.f);
        float v3 = fmaxf(a3 * invd + b0.w, 0.f);
        float v4 = fmaxf(a4 * invd + b1.x, 0.f);
        float v5 = fmaxf(a5 * invd + b1.y, 0.f);
        float v6 = fmaxf(a6 * invd + b1.z, 0.f);
        float v7 = fmaxf(a7 * invd + b1.w, 0.f);
        uint4 o;
        asm("cvt.rn.bf16x2.f32 %0, %1, %2;" : "=r"(o.x) : "f"(v1), "f"(v0));
        asm("cvt.rn.bf16x2.f32 %0, %1, %2;" : "=r"(o.y) : "f"(v3), "f"(v2));
        asm("cvt.rn.bf16x2.f32 %0, %1, %2;" : "=r"(o.z) : "f"(v5), "f"(v4));
        asm("cvt.rn.bf16x2.f32 %0, %1, %2;" : "=r"(o.w) : "f"(v7), "f"(v6));
        g_outb[w * 16 + l16] = o;
    }
}

// ---------------------------------------------------------------------------
// Layer 2 GEMM via mma.sync (HMMA): g_hb = bf16((g_outb @ W2) * dinv)
// CTA: 128 rows x N=128 x K=128. 8 warps; warp = m16 x n128 (16 frags).
__global__ __launch_bounds__(256) void gemm2_hmma_kernel() {
    extern __shared__ __align__(16) uint8_t smem[];
    uint8_t* sA = smem;
    uint8_t* sB = smem + 128 * PITCH;

    int tid = threadIdx.x, wid = tid >> 5, lane = tid & 31;
    int row0 = blockIdx.x * TILE_M;

    const uint4 zero4 = make_uint4(0, 0, 0, 0);
    for (int g = tid; g < 2048; g += 256) {
        int row = g >> 4, ch = g & 15;
        uint4 va = (row0 + row < N_NODES) ? g_outb[(row0 + row) * 16 + ch] : zero4;
        *(uint4*)(sA + row * PITCH + ch * 16) = va;
        *(uint4*)(sB + row * PITCH + ch * 16) = g_w2tb[g];
    }
    __syncthreads();

    float acc[16][4];
#pragma unroll
    for (int f = 0; f < 16; f++)
#pragma unroll
        for (int j = 0; j < 4; j++) acc[f][j] = 0.f;

    int r = lane >> 2;
    int kc2 = (lane & 3) * 4;
    uint32_t aAddr = smem_u32(sA) + (wid * 16 + r) * PITCH + kc2;
    uint32_t bAddr = smem_u32(sB) + r * PITCH + kc2;

#pragma unroll
    for (int ks = 0; ks < 8; ks++) {
        uint32_t a0, a1, a2, a3;
        uint32_t ka = aAddr + ks * 32;
        asm volatile("ld.shared.b32 %0,[%1];" : "=r"(a0) : "r"(ka));
        asm volatile("ld.shared.b32 %0,[%1];" : "=r"(a1) : "r"(ka + 8 * PITCH));
        asm volatile("ld.shared.b32 %0,[%1];" : "=r"(a2) : "r"(ka + 16));
        asm volatile("ld.shared.b32 %0,[%1];" : "=r"(a3) : "r"(ka + 8 * PITCH + 16));
#pragma unroll
        for (int f = 0; f < 16; f++) {
            uint32_t b0, b1;
            uint32_t kb = bAddr + ks * 32 + f * 8 * PITCH;
            asm volatile("ld.shared.b32 %0,[%1];" : "=r"(b0) : "r"(kb));
            asm volatile("ld.shared.b32 %0,[%1];" : "=r"(b1) : "r"(kb + 16));
            asm volatile(
                "mma.sync.aligned.m16n8k16.row.col.f32.bf16.bf16.f32 "
                "{%0,%1,%2,%3},{%4,%5,%6,%7},{%8,%9},{%0,%1,%2,%3};"
                : "+f"(acc[f][0]), "+f"(acc[f][1]), "+f"(acc[f][2]), "+f"(acc[f][3])
                : "r"(a0), "r"(a1), "r"(a2), "r"(a3), "r"(b0), "r"(b1));
        }
    }

    int rlo = row0 + wid * 16 + r;
    int rhi = rlo + 8;
    float dlo = (rlo < N_NODES) ? g_dinv[rlo] : 0.f;
    float dhi = (rhi < N_NODES) ? g_dinv[rhi] : 0.f;
    uint32_t* ghw = (uint32_t*)g_hb;
    int wcol = (lane & 3);
#pragma unroll
    for (int f = 0; f < 16; f++) {
        uint32_t plo, phi;
        asm("cvt.rn.bf16x2.f32 %0, %1, %2;" : "=r"(plo)
            : "f"(acc[f][1] * dlo), "f"(acc[f][0] * dlo));
        asm("cvt.rn.bf16x2.f32 %0, %1, %2;" : "=r"(phi)
            : "f"(acc[f][3] * dhi), "f"(acc[f][2] * dhi));
        if (rlo < N_NODES) ghw[rlo * 64 + f * 4 + wcol] = plo;
        if (rhi < N_NODES) ghw[rhi * 64 + f * 4 + wcol] = phi;
    }
}

// ---------------------------------------------------------------------------
// Pool + head fused: block per graph (batch sorted). Input g_outb (bf16).
__global__ void pool_head_kernel(const int* __restrict__ batch_raw,
                                 const float* __restrict__ Wl,
                                 const float* __restrict__ bl,
                                 float* __restrict__ out) {
    int g = blockIdx.x;
    int tid = threadIdx.x;
    int is64 = g_is64;

    int lo = 0, hi = N_NODES;
    while (lo < hi) {
        int mid = (lo + hi) >> 1;
        if (idx_at(batch_raw, mid, is64) < g) lo = mid + 1; else hi = mid;
    }
    int beg = lo;
    hi = N_NODES;
    while (lo < hi) {
        int mid = (lo + hi) >> 1;
        if (idx_at(batch_raw, mid, is64) < g + 1) lo = mid + 1; else hi = mid;
    }
    int end = lo;

    const __nv_bfloat16* outb = (const __nv_bfloat16*)g_outb;
    float acc = 0.f;
    for (int n = beg; n < end; n++)
        acc += __bfloat162float(outb[n * HIDDEN + tid]);

    float v = acc * __ldg(Wl + tid);
    __shared__ float wsum[4];
#pragma unroll
    for (int off = 16; off; off >>= 1) v += __shfl_down_sync(0xffffffffu, v, off);
    if ((tid & 31) == 0) wsum[tid >> 5] = v;
    __syncthreads();
    if (tid == 0) {
        float tot = wsum[0] + wsum[1] + wsum[2] + wsum[3];
        float cnt = fmaxf((float)(end - beg), 1.0f);
        out[g] = tot / cnt + __ldg(bl);
    }
}

// ---------------------------------------------------------------------------
extern "C" void kernel_launch(void* const* d_in, const int* in_sizes, int n_in,
                              void* d_out, int out_size) {
    const float* x = (const float*)d_in[0];
    const int* ei_raw = (const int*)d_in[1];
    const int* batch_raw = (const int*)d_in[2];
    const float* W1 = (const float*)d_in[3];
    const float* b1 = (const float*)d_in[4];
    const float* W2 = (const float*)d_in[5];
    const float* b2 = (const float*)d_in[6];
    const float* Wl = (const float*)d_in[7];
    const float* bl = (const float*)d_in[8];
    float* out = (float*)d_out;

    cudaFuncSetAttribute(gemm2_hmma_kernel,
                         cudaFuncAttributeMaxDynamicSharedMemorySize, SM_GEMM2);

    void *p_deg = nullptr, *p_cur = nullptr;
    cudaGetSymbolAddress(&p_deg, g_deg);
    cudaGetSymbolAddress(&p_cur, g_cursor);
    cudaMemsetAsync(p_deg, 0, N_NODES * sizeof(int));
    cudaMemsetAsync(p_cur, 0, N_NODES * sizeof(int));

    w2cvt_kernel<<<8, 256>>>(W2, ei_raw);
    deg_kernel<<<(N_EDGES + 255) / 256, 256>>>(ei_raw);

    blocksum_kernel<<<NB, SCAN_B>>>();
    rowstart_kernel<<<NB, SCAN_B>>>();
    bin_kernel<<<(N_EDGES + 255) / 256, 256>>>(ei_raw);

    gemm1_kernel<<<(N_NODES + 7) / 8, 256>>>(x, W1);
    gather_kernel<<<(N_NODES + 7) / 8, 256>>>(b1);

    gemm2_hmma_kernel<<<GRID2, 256, SM_GEMM2>>>();
    gather_kernel<<<(N_NODES + 7) / 8, 256>>>(b2);

    pool_head_kernel<<<N_GRAPHS, 128>>>(batch_raw, Wl, bl, out);
}

// round 9
// speedup vs baseline: 1.5479x; 1.0087x over previous
#include <cuda_runtime.h>
#include <cuda_bf16.h>
#include <cstdint>

#define N_NODES 100000
#define N_EDGES 1600000
#define N_FEAT  16
#define HIDDEN  128
#define N_GRAPHS 512
#define HU2 (HIDDEN / 4)          // 32 uint2 (4 bf16) per node row
#define SCAN_B 1024
#define NB ((N_NODES + SCAN_B - 1) / SCAN_B)   // 98
#define TILE_M 128
#define GRID2 ((N_NODES + TILE_M - 1) / TILE_M)  // 782
#define PITCH 272                 // smem row pitch (bytes): conflict-free frag loads
#define SM_GEMM2 (2 * 128 * PITCH)  // 69632 dynamic smem

// ---- scratch ----
__device__ uint4  g_hb[N_NODES * 16];     // h*dinv, bf16 rows (gather in / gemm out)
__device__ uint4  g_outb[N_NODES * 16];   // relu(out+b), bf16 rows (gemm2 A / pool in)
__device__ uint4  g_w2tb[128 * 16];       // W2^T as bf16 [n][k]
__device__ float  g_dinv[N_NODES];
__device__ int    g_deg[N_NODES];
__device__ int    g_cursor[N_NODES];
__device__ int    g_row_start[N_NODES + 1];
__device__ int    g_blocksum[NB];
__device__ int    g_csr_src[N_EDGES];

__device__ __forceinline__ int idx_at(const int* __restrict__ p, int i, int is64) {
    return is64 ? p[2 * i] : p[i];
}

// Lane-parallel dtype detect: indices < 2^31, random — if int64, odd words all 0.
__device__ __forceinline__ int detect64(const int* __restrict__ p) {
    int lane = threadIdx.x & 31;
    int z = (p[2 * lane + 1] == 0);
    return __all_sync(0xffffffffu, z);
}

__device__ __forceinline__ uint32_t smem_u32(const void* p) {
    uint32_t a;
    asm("{ .reg .u64 t; cvta.to.shared.u64 t, %1; cvt.u32.u64 %0, t; }" : "=r"(a) : "l"(p));
    return a;
}

// ---------------------------------------------------------------------------
// W2 -> W2tb[n][k] bf16 (transposed)
__global__ void w2cvt_kernel(const float* __restrict__ W2) {
    int t = blockIdx.x * 256 + threadIdx.x;
    if (t >= 128 * 16) return;
    int n = t >> 4, ch = t & 15;
    int k0 = ch * 8;
    uint32_t w[4];
#pragma unroll
    for (int j = 0; j < 4; j++) {
        float lo = W2[(k0 + 2 * j) * HIDDEN + n];
        float hi = W2[(k0 + 2 * j + 1) * HIDDEN + n];
        asm("cvt.rn.bf16x2.f32 %0, %1, %2;" : "=r"(w[j]) : "f"(hi), "f"(lo));
    }
    g_w2tb[t] = make_uint4(w[0], w[1], w[2], w[3]);
}

__global__ void deg_kernel(const int* __restrict__ ei_raw) {
    int is64 = detect64(ei_raw);
    int e = blockIdx.x * blockDim.x + threadIdx.x;
    if (e >= N_EDGES) return;
    const int* dst = ei_raw + (is64 ? 2 * N_EDGES : N_EDGES);
    atomicAdd(&g_deg[idx_at(dst, e, is64)], 1);
}

__global__ void dinv_kernel() {
    int i = blockIdx.x * blockDim.x + threadIdx.x;
    if (i < N_NODES) g_dinv[i] = rsqrtf((float)g_deg[i] + 1.0f);
}

__global__ void blocksum_kernel() {
    __shared__ int wsum[32];
    int b = blockIdx.x, tid = threadIdx.x;
    int i = b * SCAN_B + tid;
    int v = (i < N_NODES) ? g_deg[i] : 0;
#pragma unroll
    for (int off = 16; off; off >>= 1) v += __shfl_down_sync(0xffffffffu, v, off);
    if ((tid & 31) == 0) wsum[tid >> 5] = v;
    __syncthreads();
    if (tid < 32) {
        int s = (tid < SCAN_B / 32) ? wsum[tid] : 0;
#pragma unroll
        for (int off = 16; off; off >>= 1) s += __shfl_down_sync(0xffffffffu, s, off);
        if (tid == 0) g_blocksum[b] = s;
    }
}

// rowstart: hierarchical shfl scan (2 barriers) + inline prefix of blocksums
__global__ void rowstart_kernel() {
    __shared__ int wsum[32];
    __shared__ int s_pref;
    int b = blockIdx.x, tid = threadIdx.x;
    int lane = tid & 31, wrp = tid >> 5;

    if (tid < 32) {                       // prefix of blocksum[0..b)
        int sum = 0;
        for (int j = tid; j < b; j += 32) sum += g_blocksum[j];
#pragma unroll
        for (int off = 16; off; off >>= 1) sum += __shfl_down_sync(0xffffffffu, sum, off);
        if (tid == 0) s_pref = sum;
    }

    int i = b * SCAN_B + tid;
    int v = (i < N_NODES) ? g_deg[i] : 0;
    int sv = v;
#pragma unroll
    for (int off = 1; off < 32; off <<= 1) {
        int t = __shfl_up_sync(0xffffffffu, sv, off);
        if (lane >= off) sv += t;
    }
    if (lane == 31) wsum[wrp] = sv;
    __syncthreads();
    if (wrp == 0) {
        int s = wsum[lane];
#pragma unroll
        for (int off = 1; off < 32; off <<= 1) {
            int t = __shfl_up_sync(0xffffffffu, s, off);
            if (lane >= off) s += t;
        }
        wsum[lane] = s;
    }
    __syncthreads();
    int incl = sv + (wrp ? wsum[wrp - 1] : 0);
    int excl = incl - v + s_pref;
    if (i < N_NODES) g_row_start[i] = excl;
    if (i == N_NODES - 1) g_row_start[N_NODES] = excl + v;
}

__global__ void bin_kernel(const int* __restrict__ ei_raw) {
    int is64 = detect64(ei_raw);
    int e = blockIdx.x * blockDim.x + threadIdx.x;
    if (e >= N_EDGES) return;
    const int* src = ei_raw;
    const int* dst = ei_raw + (is64 ? 2 * N_EDGES : N_EDGES);
    int d = idx_at(dst, e, is64);
    int pos = atomicAdd(&g_cursor[d], 1);
    g_csr_src[g_row_start[d] + pos] = idx_at(src, e, is64);
}

// ---------------------------------------------------------------------------
// Layer 1 GEMM: g_hb = bf16( (x @ W1) * dinv )   (K=16). Warp/node, 4 cols/lane.
__global__ void gemm1_kernel(const float* __restrict__ x,
                             const float* __restrict__ W1) {
    __shared__ float sW[N_FEAT * HIDDEN];
    int tid = threadIdx.x;
    for (int j = tid; j < N_FEAT * HIDDEN; j += 256) sW[j] = W1[j];
    __syncthreads();

    int node = blockIdx.x * 8 + (tid >> 5);
    int lane = tid & 31;
    if (node >= N_NODES) return;

    const float* xr = x + node * N_FEAT;
    float xv[N_FEAT];
#pragma unroll
    for (int k = 0; k < N_FEAT; k++) xv[k] = __ldg(xr + k);

    int c = lane * 4;
    float4 acc = make_float4(0.f, 0.f, 0.f, 0.f);
#pragma unroll
    for (int k = 0; k < N_FEAT; k++) {
        const float* w = sW + k * HIDDEN + c;
        acc.x += xv[k] * w[0];
        acc.y += xv[k] * w[1];
        acc.z += xv[k] * w[2];
        acc.w += xv[k] * w[3];
    }
    float dv = g_dinv[node];
    __nv_bfloat162 p0 = __float22bfloat162_rn(make_float2(acc.x * dv, acc.y * dv));
    __nv_bfloat162 p1 = __float22bfloat162_rn(make_float2(acc.z * dv, acc.w * dv));
    uint2 u;
    *(__nv_bfloat162*)&u.x = p0;
    *(__nv_bfloat162*)&u.y = p1;
    ((uint2*)g_hb)[node * HU2 + lane] = u;
}

// ---------------------------------------------------------------------------
// CSR gather: v = dinv[d]*(h_pre[d] + Σ_s h_pre[s]) + bias;  g_outb = bf16(relu(v))
// Warp per dst node; half-warp per edge, uint4 (8 bf16) per lane.
__global__ void gather_kernel(const float* __restrict__ bias) {
    int w = (blockIdx.x * blockDim.x + threadIdx.x) >> 5;
    int lane = threadIdx.x & 31;
    if (w >= N_NODES) return;

    int beg = g_row_start[w];
    int end = g_row_start[w + 1];
    int half = lane >> 4;
    int l16 = lane & 15;

    float a0 = 0.f, a1 = 0.f, a2 = 0.f, a3 = 0.f;
    float a4 = 0.f, a5 = 0.f, a6 = 0.f, a7 = 0.f;

    int i = beg;
    for (; i + 1 < end; i += 2) {
        int s = g_csr_src[i + half];
        uint4 v = g_hb[s * 16 + l16];
        float2 f0 = __bfloat1622float2(*(__nv_bfloat162*)&v.x);
        float2 f1 = __bfloat1622float2(*(__nv_bfloat162*)&v.y);
        float2 f2 = __bfloat1622float2(*(__nv_bfloat162*)&v.z);
        float2 f3 = __bfloat1622float2(*(__nv_bfloat162*)&v.w);
        a0 += f0.x; a1 += f0.y; a2 += f1.x; a3 += f1.y;
        a4 += f2.x; a5 += f2.y; a6 += f3.x; a7 += f3.y;
    }
    if (i < end && half == 0) {
        int s = g_csr_src[i];
        uint4 v = g_hb[s * 16 + l16];
        float2 f0 = __bfloat1622float2(*(__nv_bfloat162*)&v.x);
        float2 f1 = __bfloat1622float2(*(__nv_bfloat162*)&v.y);
        float2 f2 = __bfloat1622float2(*(__nv_bfloat162*)&v.z);
        float2 f3 = __bfloat1622float2(*(__nv_bfloat162*)&v.w);
        a0 += f0.x; a1 += f0.y; a2 += f1.x; a3 += f1.y;
        a4 += f2.x; a5 += f2.y; a6 += f3.x; a7 += f3.y;
    }

    a0 += __shfl_xor_sync(0xffffffffu, a0, 16);
    a1 += __shfl_xor_sync(0xffffffffu, a1, 16);
    a2 += __shfl_xor_sync(0xffffffffu, a2, 16);
    a3 += __shfl_xor_sync(0xffffffffu, a3, 16);
    a4 += __shfl_xor_sync(0xffffffffu, a4, 16);
    a5 += __shfl_xor_sync(0xffffffffu, a5, 16);
    a6 += __shfl_xor_sync(0xffffffffu, a6, 16);
    a7 += __shfl_xor_sync(0xffffffffu, a7, 16);

    if (half == 0) {
        uint4 v = g_hb[w * 16 + l16];
        float2 f0 = __bfloat1622float2(*(__nv_bfloat162*)&v.x);
        float2 f1 = __bfloat1622float2(*(__nv_bfloat162*)&v.y);
        float2 f2 = __bfloat1622float2(*(__nv_bfloat162*)&v.z);
        float2 f3 = __bfloat1622float2(*(__nv_bfloat162*)&v.w);
        a0 += f0.x; a1 += f0.y; a2 += f1.x; a3 += f1.y;
        a4 += f2.x; a5 += f2.y; a6 += f3.x; a7 += f3.y;

        float invd = g_dinv[w];
        float4 b0 = ((const float4*)bias)[l16 * 2];
        float4 b1 = ((const float4*)bias)[l16 * 2 + 1];
        float v0 = fmaxf(a0 * invd + b0.x, 0.f);
        float v1 = fmaxf(a1 * invd + b0.y, 0.f);
        float v2 = fmaxf(a2 * invd + b0.z, 0.f);
        float v3 = fmaxf(a3 * invd + b0.w, 0.f);
        float v4 = fmaxf(a4 * invd + b1.x, 0.f);
        float v5 = fmaxf(a5 * invd + b1.y, 0.f);
        float v6 = fmaxf(a6 * invd + b1.z, 0.f);
        float v7 = fmaxf(a7 * invd + b1.w, 0.f);
        uint4 o;
        asm("cvt.rn.bf16x2.f32 %0, %1, %2;" : "=r"(o.x) : "f"(v1), "f"(v0));
        asm("cvt.rn.bf16x2.f32 %0, %1, %2;" : "=r"(o.y) : "f"(v3), "f"(v2));
        asm("cvt.rn.bf16x2.f32 %0, %1, %2;" : "=r"(o.z) : "f"(v5), "f"(v4));
        asm("cvt.rn.bf16x2.f32 %0, %1, %2;" : "=r"(o.w) : "f"(v7), "f"(v6));
        g_outb[w * 16 + l16] = o;
    }
}

// ---------------------------------------------------------------------------
// Layer 2 GEMM via mma.sync (HMMA): g_hb = bf16((g_outb @ W2) * dinv)
__global__ __launch_bounds__(256) void gemm2_hmma_kernel() {
    extern __shared__ __align__(16) uint8_t smem[];
    uint8_t* sA = smem;
    uint8_t* sB = smem + 128 * PITCH;

    int tid = threadIdx.x, wid = tid >> 5, lane = tid & 31;
    int row0 = blockIdx.x * TILE_M;

    const uint4 zero4 = make_uint4(0, 0, 0, 0);
    for (int g = tid; g < 2048; g += 256) {
        int row = g >> 4, ch = g & 15;
        uint4 va = (row0 + row < N_NODES) ? g_outb[(row0 + row) * 16 + ch] : zero4;
        *(uint4*)(sA + row * PITCH + ch * 16) = va;
        *(uint4*)(sB + row * PITCH + ch * 16) = g_w2tb[g];
    }
    __syncthreads();

    float acc[16][4];
#pragma unroll
    for (int f = 0; f < 16; f++)
#pragma unroll
        for (int j = 0; j < 4; j++) acc[f][j] = 0.f;

    int r = lane >> 2;
    int kc2 = (lane & 3) * 4;
    uint32_t aAddr = smem_u32(sA) + (wid * 16 + r) * PITCH + kc2;
    uint32_t bAddr = smem_u32(sB) + r * PITCH + kc2;

#pragma unroll
    for (int ks = 0; ks < 8; ks++) {
        uint32_t a0, a1, a2, a3;
        uint32_t ka = aAddr + ks * 32;
        asm volatile("ld.shared.b32 %0,[%1];" : "=r"(a0) : "r"(ka));
        asm volatile("ld.shared.b32 %0,[%1];" : "=r"(a1) : "r"(ka + 8 * PITCH));
        asm volatile("ld.shared.b32 %0,[%1];" : "=r"(a2) : "r"(ka + 16));
        asm volatile("ld.shared.b32 %0,[%1];" : "=r"(a3) : "r"(ka + 8 * PITCH + 16));
#pragma unroll
        for (int f = 0; f < 16; f++) {
            uint32_t b0, b1;
            uint32_t kb = bAddr + ks * 32 + f * 8 * PITCH;
            asm volatile("ld.shared.b32 %0,[%1];" : "=r"(b0) : "r"(kb));
            asm volatile("ld.shared.b32 %0,[%1];" : "=r"(b1) : "r"(kb + 16));
            asm volatile(
                "mma.sync.aligned.m16n8k16.row.col.f32.bf16.bf16.f32 "
                "{%0,%1,%2,%3},{%4,%5,%6,%7},{%8,%9},{%0,%1,%2,%3};"
                : "+f"(acc[f][0]), "+f"(acc[f][1]), "+f"(acc[f][2]), "+f"(acc[f][3])
                : "r"(a0), "r"(a1), "r"(a2), "r"(a3), "r"(b0), "r"(b1));
        }
    }

    int rlo = row0 + wid * 16 + r;
    int rhi = rlo + 8;
    float dlo = (rlo < N_NODES) ? g_dinv[rlo] : 0.f;
    float dhi = (rhi < N_NODES) ? g_dinv[rhi] : 0.f;
    uint32_t* ghw = (uint32_t*)g_hb;
    int wcol = (lane & 3);
#pragma unroll
    for (int f = 0; f < 16; f++) {
        uint32_t plo, phi;
        asm("cvt.rn.bf16x2.f32 %0, %1, %2;" : "=r"(plo)
            : "f"(acc[f][1] * dlo), "f"(acc[f][0] * dlo));
        asm("cvt.rn.bf16x2.f32 %0, %1, %2;" : "=r"(phi)
            : "f"(acc[f][3] * dhi), "f"(acc[f][2] * dhi));
        if (rlo < N_NODES) ghw[rlo * 64 + f * 4 + wcol] = plo;
        if (rhi < N_NODES) ghw[rhi * 64 + f * 4 + wcol] = phi;
    }
}

// ---------------------------------------------------------------------------
// Pool + head fused: block per graph (batch sorted). Input g_outb (bf16).
__global__ void pool_head_kernel(const int* __restrict__ batch_raw,
                                 const int* __restrict__ ei_raw,
                                 const float* __restrict__ Wl,
                                 const float* __restrict__ bl,
                                 float* __restrict__ out) {
    int g = blockIdx.x;
    int tid = threadIdx.x;
    int is64 = detect64(ei_raw);

    int lo = 0, hi = N_NODES;
    while (lo < hi) {
        int mid = (lo + hi) >> 1;
        if (idx_at(batch_raw, mid, is64) < g) lo = mid + 1; else hi = mid;
    }
    int beg = lo;
    hi = N_NODES;
    while (lo < hi) {
        int mid = (lo + hi) >> 1;
        if (idx_at(batch_raw, mid, is64) < g + 1) lo = mid + 1; else hi = mid;
    }
    int end = lo;

    const __nv_bfloat16* outb = (const __nv_bfloat16*)g_outb;
    float acc = 0.f;
    for (int n = beg; n < end; n++)
        acc += __bfloat162float(outb[n * HIDDEN + tid]);

    float v = acc * __ldg(Wl + tid);
    __shared__ float wsum[4];
#pragma unroll
    for (int off = 16; off; off >>= 1) v += __shfl_down_sync(0xffffffffu, v, off);
    if ((tid & 31) == 0) wsum[tid >> 5] = v;
    __syncthreads();
    if (tid == 0) {
        float tot = wsum[0] + wsum[1] + wsum[2] + wsum[3];
        float cnt = fmaxf((float)(end - beg), 1.0f);
        out[g] = tot / cnt + __ldg(bl);
    }
}

// ---------------------------------------------------------------------------
extern "C" void kernel_launch(void* const* d_in, const int* in_sizes, int n_in,
                              void* d_out, int out_size) {
    const float* x = (const float*)d_in[0];
    const int* ei_raw = (const int*)d_in[1];
    const int* batch_raw = (const int*)d_in[2];
    const float* W1 = (const float*)d_in[3];
    const float* b1 = (const float*)d_in[4];
    const float* W2 = (const float*)d_in[5];
    const float* b2 = (const float*)d_in[6];
    const float* Wl = (const float*)d_in[7];
    const float* bl = (const float*)d_in[8];
    float* out = (float*)d_out;

    static cudaStream_t s1 = nullptr;
    static cudaEvent_t evF = nullptr, evD = nullptr, evJ = nullptr;
    if (!s1) {
        cudaStreamCreate(&s1);
        cudaEventCreateWithFlags(&evF, cudaEventDisableTiming);
        cudaEventCreateWithFlags(&evD, cudaEventDisableTiming);
        cudaEventCreateWithFlags(&evJ, cudaEventDisableTiming);
        cudaFuncSetAttribute(gemm2_hmma_kernel,
                             cudaFuncAttributeMaxDynamicSharedMemorySize, SM_GEMM2);
    }

    void *p_deg = nullptr, *p_cur = nullptr;
    cudaGetSymbolAddress(&p_deg, g_deg);
    cudaGetSymbolAddress(&p_cur, g_cursor);
    cudaMemsetAsync(p_deg, 0, N_NODES * sizeof(int));
    cudaMemsetAsync(p_cur, 0, N_NODES * sizeof(int));

    // Fork: side stream does W2 conversion (no deps)
    cudaEventRecord(evF, 0);
    cudaStreamWaitEvent(s1, evF, 0);
    w2cvt_kernel<<<8, 256, 0, s1>>>(W2);

    // Main: degree -> dinv
    deg_kernel<<<(N_EDGES + 255) / 256, 256>>>(ei_raw);
    dinv_kernel<<<(N_NODES + 255) / 256, 256>>>();
    cudaEventRecord(evD, 0);

    // Side: gemm1 (needs dinv) overlapped with scan+bin on main
    cudaStreamWaitEvent(s1, evD, 0);
    gemm1_kernel<<<(N_NODES + 7) / 8, 256, 0, s1>>>(x, W1);
    cudaEventRecord(evJ, s1);

    blocksum_kernel<<<NB, SCAN_B>>>();
    rowstart_kernel<<<NB, SCAN_B>>>();
    bin_kernel<<<(N_EDGES + 255) / 256, 256>>>(ei_raw);

    // Join, then the serial back half
    cudaStreamWaitEvent(0, evJ, 0);
    gather_kernel<<<(N_NODES + 7) / 8, 256>>>(b1);
    gemm2_hmma_kernel<<<GRID2, 256, SM_GEMM2>>>();
    gather_kernel<<<(N_NODES + 7) / 8, 256>>>(b2);
    pool_head_kernel<<<N_GRAPHS, 128>>>(batch_raw, ei_raw, Wl, bl, out);
}

// round 10
// speedup vs baseline: 1.7007x; 1.0987x over previous
#include <cuda_runtime.h>
#include <cuda_bf16.h>
#include <cstdint>

#define N_NODES 100000
#define N_EDGES 1600000
#define N_FEAT  16
#define HIDDEN  128
#define N_GRAPHS 512
#define HU2 (HIDDEN / 4)          // 32 uint2 (4 bf16) per node row
#define SCAN_B 1024
#define NB ((N_NODES + SCAN_B - 1) / SCAN_B)   // 98
#define TILE_M 128
#define GRID2 ((N_NODES + TILE_M - 1) / TILE_M)  // 782
#define PITCH 272                 // smem row pitch (bytes): conflict-free frag loads
#define SM_GEMM2 (2 * 128 * PITCH)  // 69632 dynamic smem
#define G1_NODES_PER_WARP 8
#define G1_GRID ((N_NODES + 8 * G1_NODES_PER_WARP - 1) / (8 * G1_NODES_PER_WARP))

// ---- scratch ----
__device__ uint4  g_hb[N_NODES * 16];     // h*dinv, bf16 rows (gather in / gemm out)
__device__ uint4  g_outb[N_NODES * 16];   // relu(out+b), bf16 rows (gemm2 A / pool in)
__device__ uint4  g_w2tb[128 * 16];       // W2^T as bf16 [n][k]
__device__ float  g_dinv[N_NODES];
__device__ int    g_deg[N_NODES];
__device__ int    g_cursor[N_NODES];
__device__ int    g_row_start[N_NODES + 1];
__device__ int    g_blocksum[NB];
__device__ int    g_csr_src[N_EDGES];

__device__ __forceinline__ int idx_at(const int* __restrict__ p, int i, int is64) {
    return is64 ? p[2 * i] : p[i];
}

// Lane-parallel dtype detect: indices < 2^31, random — if int64, odd words all 0.
__device__ __forceinline__ int detect64(const int* __restrict__ p) {
    int lane = threadIdx.x & 31;
    int z = (p[2 * lane + 1] == 0);
    return __all_sync(0xffffffffu, z);
}

__device__ __forceinline__ uint32_t smem_u32(const void* p) {
    uint32_t a;
    asm("{ .reg .u64 t; cvta.to.shared.u64 t, %1; cvt.u32.u64 %0, t; }" : "=r"(a) : "l"(p));
    return a;
}

// ---- f32x2 packed math ----
__device__ __forceinline__ unsigned long long pack2(float lo, float hi) {
    unsigned long long r;
    asm("mov.b64 %0, {%1, %2};" : "=l"(r) : "f"(lo), "f"(hi));
    return r;
}
__device__ __forceinline__ void fma2(unsigned long long& d, unsigned long long a,
                                     unsigned long long b) {
    asm("fma.rn.f32x2 %0, %1, %2, %3;" : "=l"(d) : "l"(a), "l"(b), "l"(d));
}
__device__ __forceinline__ float2 unpack2(unsigned long long v) {
    float lo, hi;
    asm("mov.b64 {%0, %1}, %2;" : "=f"(lo), "=f"(hi) : "l"(v));
    return make_float2(lo, hi);
}

// ---------------------------------------------------------------------------
// W2 -> W2tb[n][k] bf16 (transposed)
__global__ void w2cvt_kernel(const float* __restrict__ W2) {
    int t = blockIdx.x * 256 + threadIdx.x;
    if (t >= 128 * 16) return;
    int n = t >> 4, ch = t & 15;
    int k0 = ch * 8;
    uint32_t w[4];
#pragma unroll
    for (int j = 0; j < 4; j++) {
        float lo = W2[(k0 + 2 * j) * HIDDEN + n];
        float hi = W2[(k0 + 2 * j + 1) * HIDDEN + n];
        asm("cvt.rn.bf16x2.f32 %0, %1, %2;" : "=r"(w[j]) : "f"(hi), "f"(lo));
    }
    g_w2tb[t] = make_uint4(w[0], w[1], w[2], w[3]);
}

__global__ void deg_kernel(const int* __restrict__ ei_raw) {
    int is64 = detect64(ei_raw);
    int e = blockIdx.x * blockDim.x + threadIdx.x;
    if (e >= N_EDGES) return;
    const int* dst = ei_raw + (is64 ? 2 * N_EDGES : N_EDGES);
    atomicAdd(&g_deg[idx_at(dst, e, is64)], 1);
}

__global__ void dinv_kernel() {
    int i = blockIdx.x * blockDim.x + threadIdx.x;
    if (i < N_NODES) g_dinv[i] = rsqrtf((float)g_deg[i] + 1.0f);
}

__global__ void blocksum_kernel() {
    __shared__ int wsum[32];
    int b = blockIdx.x, tid = threadIdx.x;
    int i = b * SCAN_B + tid;
    int v = (i < N_NODES) ? g_deg[i] : 0;
#pragma unroll
    for (int off = 16; off; off >>= 1) v += __shfl_down_sync(0xffffffffu, v, off);
    if ((tid & 31) == 0) wsum[tid >> 5] = v;
    __syncthreads();
    if (tid < 32) {
        int s = (tid < SCAN_B / 32) ? wsum[tid] : 0;
#pragma unroll
        for (int off = 16; off; off >>= 1) s += __shfl_down_sync(0xffffffffu, s, off);
        if (tid == 0) g_blocksum[b] = s;
    }
}

// rowstart: hierarchical shfl scan (2 barriers) + inline prefix of blocksums
__global__ void rowstart_kernel() {
    __shared__ int wsum[32];
    __shared__ int s_pref;
    int b = blockIdx.x, tid = threadIdx.x;
    int lane = tid & 31, wrp = tid >> 5;

    if (tid < 32) {
        int sum = 0;
        for (int j = tid; j < b; j += 32) sum += g_blocksum[j];
#pragma unroll
        for (int off = 16; off; off >>= 1) sum += __shfl_down_sync(0xffffffffu, sum, off);
        if (tid == 0) s_pref = sum;
    }

    int i = b * SCAN_B + tid;
    int v = (i < N_NODES) ? g_deg[i] : 0;
    int sv = v;
#pragma unroll
    for (int off = 1; off < 32; off <<= 1) {
        int t = __shfl_up_sync(0xffffffffu, sv, off);
        if (lane >= off) sv += t;
    }
    if (lane == 31) wsum[wrp] = sv;
    __syncthreads();
    if (wrp == 0) {
        int s = wsum[lane];
#pragma unroll
        for (int off = 1; off < 32; off <<= 1) {
            int t = __shfl_up_sync(0xffffffffu, s, off);
            if (lane >= off) s += t;
        }
        wsum[lane] = s;
    }
    __syncthreads();
    int incl = sv + (wrp ? wsum[wrp - 1] : 0);
    int excl = incl - v + s_pref;
    if (i < N_NODES) g_row_start[i] = excl;
    if (i == N_NODES - 1) g_row_start[N_NODES] = excl + v;
}

__global__ void bin_kernel(const int* __restrict__ ei_raw) {
    int is64 = detect64(ei_raw);
    int e = blockIdx.x * blockDim.x + threadIdx.x;
    if (e >= N_EDGES) return;
    const int* src = ei_raw;
    const int* dst = ei_raw + (is64 ? 2 * N_EDGES : N_EDGES);
    int d = idx_at(dst, e, is64);
    int pos = atomicAdd(&g_cursor[d], 1);
    g_csr_src[g_row_start[d] + pos] = idx_at(src, e, is64);
}

// ---------------------------------------------------------------------------
// Layer 1 GEMM v2: W1 in registers (f32x2 pairs), 8 nodes/warp, no smem.
// g_hb = bf16( (x @ W1) * dinv ).  Each lane: 4 output cols.
__global__ __launch_bounds__(256, 2) void gemm1_kernel(const float* __restrict__ x,
                                                       const float* __restrict__ W1) {
    int lane = threadIdx.x & 31;
    int warp = blockIdx.x * 8 + (threadIdx.x >> 5);
    int c = lane * 4;

    // Preload W1 columns c..c+3 as packed pairs (coalesced LDG.128, L1-resident)
    unsigned long long w2[N_FEAT][2];
#pragma unroll
    for (int k = 0; k < N_FEAT; k++) {
        float4 w = __ldg((const float4*)(W1 + k * HIDDEN + c));
        w2[k][0] = pack2(w.x, w.y);
        w2[k][1] = pack2(w.z, w.w);
    }

    int node0 = warp * G1_NODES_PER_WARP;
#pragma unroll
    for (int t = 0; t < G1_NODES_PER_WARP; t++) {
        int node = node0 + t;
        if (node >= N_NODES) return;
        const float4* xr = (const float4*)(x + node * N_FEAT);
        unsigned long long acc0 = 0ull, acc1 = 0ull;
#pragma unroll
        for (int j = 0; j < 4; j++) {
            float4 xj = __ldg(xr + j);
            unsigned long long p;
            p = pack2(xj.x, xj.x); fma2(acc0, p, w2[4 * j + 0][0]); fma2(acc1, p, w2[4 * j + 0][1]);
            p = pack2(xj.y, xj.y); fma2(acc0, p, w2[4 * j + 1][0]); fma2(acc1, p, w2[4 * j + 1][1]);
            p = pack2(xj.z, xj.z); fma2(acc0, p, w2[4 * j + 2][0]); fma2(acc1, p, w2[4 * j + 2][1]);
            p = pack2(xj.w, xj.w); fma2(acc0, p, w2[4 * j + 3][0]); fma2(acc1, p, w2[4 * j + 3][1]);
        }
        float dv = g_dinv[node];
        float2 a0 = unpack2(acc0);
        float2 a1 = unpack2(acc1);
        uint2 u;
        asm("cvt.rn.bf16x2.f32 %0, %1, %2;" : "=r"(u.x) : "f"(a0.y * dv), "f"(a0.x * dv));
        asm("cvt.rn.bf16x2.f32 %0, %1, %2;" : "=r"(u.y) : "f"(a1.y * dv), "f"(a1.x * dv));
        ((uint2*)g_hb)[node * HU2 + lane] = u;
    }
}

// ---------------------------------------------------------------------------
// CSR gather: v = dinv[d]*(h_pre[d] + Σ_s h_pre[s]) + bias;  g_outb = bf16(relu(v))
// Warp per dst node; half-warp per edge, uint4 (8 bf16) per lane.
__global__ void gather_kernel(const float* __restrict__ bias) {
    int w = (blockIdx.x * blockDim.x + threadIdx.x) >> 5;
    int lane = threadIdx.x & 31;
    if (w >= N_NODES) return;

    int beg = g_row_start[w];
    int end = g_row_start[w + 1];
    int half = lane >> 4;
    int l16 = lane & 15;

    float a0 = 0.f, a1 = 0.f, a2 = 0.f, a3 = 0.f;
    float a4 = 0.f, a5 = 0.f, a6 = 0.f, a7 = 0.f;

    int i = beg;
    for (; i + 1 < end; i += 2) {
        int s = g_csr_src[i + half];
        uint4 v = g_hb[s * 16 + l16];
        float2 f0 = __bfloat1622float2(*(__nv_bfloat162*)&v.x);
        float2 f1 = __bfloat1622float2(*(__nv_bfloat162*)&v.y);
        float2 f2 = __bfloat1622float2(*(__nv_bfloat162*)&v.z);
        float2 f3 = __bfloat1622float2(*(__nv_bfloat162*)&v.w);
        a0 += f0.x; a1 += f0.y; a2 += f1.x; a3 += f1.y;
        a4 += f2.x; a5 += f2.y; a6 += f3.x; a7 += f3.y;
    }
    if (i < end && half == 0) {
        int s = g_csr_src[i];
        uint4 v = g_hb[s * 16 + l16];
        float2 f0 = __bfloat1622float2(*(__nv_bfloat162*)&v.x);
        float2 f1 = __bfloat1622float2(*(__nv_bfloat162*)&v.y);
        float2 f2 = __bfloat1622float2(*(__nv_bfloat162*)&v.z);
        float2 f3 = __bfloat1622float2(*(__nv_bfloat162*)&v.w);
        a0 += f0.x; a1 += f0.y; a2 += f1.x; a3 += f1.y;
        a4 += f2.x; a5 += f2.y; a6 += f3.x; a7 += f3.y;
    }

    a0 += __shfl_xor_sync(0xffffffffu, a0, 16);
    a1 += __shfl_xor_sync(0xffffffffu, a1, 16);
    a2 += __shfl_xor_sync(0xffffffffu, a2, 16);
    a3 += __shfl_xor_sync(0xffffffffu, a3, 16);
    a4 += __shfl_xor_sync(0xffffffffu, a4, 16);
    a5 += __shfl_xor_sync(0xffffffffu, a5, 16);
    a6 += __shfl_xor_sync(0xffffffffu, a6, 16);
    a7 += __shfl_xor_sync(0xffffffffu, a7, 16);

    if (half == 0) {
        uint4 v = g_hb[w * 16 + l16];
        float2 f0 = __bfloat1622float2(*(__nv_bfloat162*)&v.x);
        float2 f1 = __bfloat1622float2(*(__nv_bfloat162*)&v.y);
        float2 f2 = __bfloat1622float2(*(__nv_bfloat162*)&v.z);
        float2 f3 = __bfloat1622float2(*(__nv_bfloat162*)&v.w);
        a0 += f0.x; a1 += f0.y; a2 += f1.x; a3 += f1.y;
        a4 += f2.x; a5 += f2.y; a6 += f3.x; a7 += f3.y;

        float invd = g_dinv[w];
        float4 b0 = ((const float4*)bias)[l16 * 2];
        float4 b1 = ((const float4*)bias)[l16 * 2 + 1];
        float v0 = fmaxf(a0 * invd + b0.x, 0.f);
        float v1 = fmaxf(a1 * invd + b0.y, 0.f);
        float v2 = fmaxf(a2 * invd + b0.z, 0.f);
        float v3 = fmaxf(a3 * invd + b0.w, 0.f);
        float v4 = fmaxf(a4 * invd + b1.x, 0.f);
        float v5 = fmaxf(a5 * invd + b1.y, 0.f);
        float v6 = fmaxf(a6 * invd + b1.z, 0.f);
        float v7 = fmaxf(a7 * invd + b1.w, 0.f);
        uint4 o;
        asm("cvt.rn.bf16x2.f32 %0, %1, %2;" : "=r"(o.x) : "f"(v1), "f"(v0));
        asm("cvt.rn.bf16x2.f32 %0, %1, %2;" : "=r"(o.y) : "f"(v3), "f"(v2));
        asm("cvt.rn.bf16x2.f32 %0, %1, %2;" : "=r"(o.z) : "f"(v5), "f"(v4));
        asm("cvt.rn.bf16x2.f32 %0, %1, %2;" : "=r"(o.w) : "f"(v7), "f"(v6));
        g_outb[w * 16 + l16] = o;
    }
}

// ---------------------------------------------------------------------------
// Layer 2 GEMM via mma.sync (HMMA): g_hb = bf16((g_outb @ W2) * dinv)
__global__ __launch_bounds__(256) void gemm2_hmma_kernel() {
    extern __shared__ __align__(16) uint8_t smem[];
    uint8_t* sA = smem;
    uint8_t* sB = smem + 128 * PITCH;

    int tid = threadIdx.x, wid = tid >> 5, lane = tid & 31;
    int row0 = blockIdx.x * TILE_M;

    const uint4 zero4 = make_uint4(0, 0, 0, 0);
    for (int g = tid; g < 2048; g += 256) {
        int row = g >> 4, ch = g & 15;
        uint4 va = (row0 + row < N_NODES) ? g_outb[(row0 + row) * 16 + ch] : zero4;
        *(uint4*)(sA + row * PITCH + ch * 16) = va;
        *(uint4*)(sB + row * PITCH + ch * 16) = g_w2tb[g];
    }
    __syncthreads();

    float acc[16][4];
#pragma unroll
    for (int f = 0; f < 16; f++)
#pragma unroll
        for (int j = 0; j < 4; j++) acc[f][j] = 0.f;

    int r = lane >> 2;
    int kc2 = (lane & 3) * 4;
    uint32_t aAddr = smem_u32(sA) + (wid * 16 + r) * PITCH + kc2;
    uint32_t bAddr = smem_u32(sB) + r * PITCH + kc2;

#pragma unroll
    for (int ks = 0; ks < 8; ks++) {
        uint32_t a0, a1, a2, a3;
        uint32_t ka = aAddr + ks * 32;
        asm volatile("ld.shared.b32 %0,[%1];" : "=r"(a0) : "r"(ka));
        asm volatile("ld.shared.b32 %0,[%1];" : "=r"(a1) : "r"(ka + 8 * PITCH));
        asm volatile("ld.shared.b32 %0,[%1];" : "=r"(a2) : "r"(ka + 16));
        asm volatile("ld.shared.b32 %0,[%1];" : "=r"(a3) : "r"(ka + 8 * PITCH + 16));
#pragma unroll
        for (int f = 0; f < 16; f++) {
            uint32_t b0, b1;
            uint32_t kb = bAddr + ks * 32 + f * 8 * PITCH;
            asm volatile("ld.shared.b32 %0,[%1];" : "=r"(b0) : "r"(kb));
            asm volatile("ld.shared.b32 %0,[%1];" : "=r"(b1) : "r"(kb + 16));
            asm volatile(
                "mma.sync.aligned.m16n8k16.row.col.f32.bf16.bf16.f32 "
                "{%0,%1,%2,%3},{%4,%5,%6,%7},{%8,%9},{%0,%1,%2,%3};"
                : "+f"(acc[f][0]), "+f"(acc[f][1]), "+f"(acc[f][2]), "+f"(acc[f][3])
                : "r"(a0), "r"(a1), "r"(a2), "r"(a3), "r"(b0), "r"(b1));
        }
    }

    int rlo = row0 + wid * 16 + r;
    int rhi = rlo + 8;
    float dlo = (rlo < N_NODES) ? g_dinv[rlo] : 0.f;
    float dhi = (rhi < N_NODES) ? g_dinv[rhi] : 0.f;
    uint32_t* ghw = (uint32_t*)g_hb;
    int wcol = (lane & 3);
#pragma unroll
    for (int f = 0; f < 16; f++) {
        uint32_t plo, phi;
        asm("cvt.rn.bf16x2.f32 %0, %1, %2;" : "=r"(plo)
            : "f"(acc[f][1] * dlo), "f"(acc[f][0] * dlo));
        asm("cvt.rn.bf16x2.f32 %0, %1, %2;" : "=r"(phi)
            : "f"(acc[f][3] * dhi), "f"(acc[f][2] * dhi));
        if (rlo < N_NODES) ghw[rlo * 64 + f * 4 + wcol] = plo;
        if (rhi < N_NODES) ghw[rhi * 64 + f * 4 + wcol] = phi;
    }
}

// ---------------------------------------------------------------------------
// Pool + head fused: block per graph (batch sorted). Input g_outb (bf16).
__global__ void pool_head_kernel(const int* __restrict__ batch_raw,
                                 const int* __restrict__ ei_raw,
                                 const float* __restrict__ Wl,
                                 const float* __restrict__ bl,
                                 float* __restrict__ out) {
    int g = blockIdx.x;
    int tid = threadIdx.x;
    int is64 = detect64(ei_raw);

    int lo = 0, hi = N_NODES;
    while (lo < hi) {
        int mid = (lo + hi) >> 1;
        if (idx_at(batch_raw, mid, is64) < g) lo = mid + 1; else hi = mid;
    }
    int beg = lo;
    hi = N_NODES;
    while (lo < hi) {
        int mid = (lo + hi) >> 1;
        if (idx_at(batch_raw, mid, is64) < g + 1) lo = mid + 1; else hi = mid;
    }
    int end = lo;

    const __nv_bfloat16* outb = (const __nv_bfloat16*)g_outb;
    float acc = 0.f;
    for (int n = beg; n < end; n++)
        acc += __bfloat162float(outb[n * HIDDEN + tid]);

    float v = acc * __ldg(Wl + tid);
    __shared__ float wsum[4];
#pragma unroll
    for (int off = 16; off; off >>= 1) v += __shfl_down_sync(0xffffffffu, v, off);
    if ((tid & 31) == 0) wsum[tid >> 5] = v;
    __syncthreads();
    if (tid == 0) {
        float tot = wsum[0] + wsum[1] + wsum[2] + wsum[3];
        float cnt = fmaxf((float)(end - beg), 1.0f);
        out[g] = tot / cnt + __ldg(bl);
    }
}

// ---------------------------------------------------------------------------
extern "C" void kernel_launch(void* const* d_in, const int* in_sizes, int n_in,
                              void* d_out, int out_size) {
    const float* x = (const float*)d_in[0];
    const int* ei_raw = (const int*)d_in[1];
    const int* batch_raw = (const int*)d_in[2];
    const float* W1 = (const float*)d_in[3];
    const float* b1 = (const float*)d_in[4];
    const float* W2 = (const float*)d_in[5];
    const float* b2 = (const float*)d_in[6];
    const float* Wl = (const float*)d_in[7];
    const float* bl = (const float*)d_in[8];
    float* out = (float*)d_out;

    static cudaStream_t s1 = nullptr;
    static cudaEvent_t evF = nullptr, evD = nullptr, evJ = nullptr;
    if (!s1) {
        cudaStreamCreate(&s1);
        cudaEventCreateWithFlags(&evF, cudaEventDisableTiming);
        cudaEventCreateWithFlags(&evD, cudaEventDisableTiming);
        cudaEventCreateWithFlags(&evJ, cudaEventDisableTiming);
        cudaFuncSetAttribute(gemm2_hmma_kernel,
                             cudaFuncAttributeMaxDynamicSharedMemorySize, SM_GEMM2);
    }

    void *p_deg = nullptr, *p_cur = nullptr;
    cudaGetSymbolAddress(&p_deg, g_deg);
    cudaGetSymbolAddress(&p_cur, g_cursor);
    cudaMemsetAsync(p_deg, 0, N_NODES * sizeof(int));
    cudaMemsetAsync(p_cur, 0, N_NODES * sizeof(int));

    // Fork: side stream does W2 conversion (no deps)
    cudaEventRecord(evF, 0);
    cudaStreamWaitEvent(s1, evF, 0);
    w2cvt_kernel<<<8, 256, 0, s1>>>(W2);

    // Main: degree -> dinv
    deg_kernel<<<(N_EDGES + 255) / 256, 256>>>(ei_raw);
    dinv_kernel<<<(N_NODES + 255) / 256, 256>>>();
    cudaEventRecord(evD, 0);

    // Side: gemm1 (needs dinv) overlapped with scan+bin on main
    cudaStreamWaitEvent(s1, evD, 0);
    gemm1_kernel<<<G1_GRID, 256, 0, s1>>>(x, W1);
    cudaEventRecord(evJ, s1);

    blocksum_kernel<<<NB, SCAN_B>>>();
    rowstart_kernel<<<NB, SCAN_B>>>();
    bin_kernel<<<(N_EDGES + 255) / 256, 256>>>(ei_raw);

    // Join, then the serial back half
    cudaStreamWaitEvent(0, evJ, 0);
    gather_kernel<<<(N_NODES + 7) / 8, 256>>>(b1);
    gemm2_hmma_kernel<<<GRID2, 256, SM_GEMM2>>>();
    gather_kernel<<<(N_NODES + 7) / 8, 256>>>(b2);
    pool_head_kernel<<<N_GRAPHS, 128>>>(batch_raw, ei_raw, Wl, bl, out);
}

// round 11
// speedup vs baseline: 1.7856x; 1.0499x over previous
#include <cuda_runtime.h>
#include <cuda_bf16.h>
#include <cstdint>

#define N_NODES 100000
#define N_EDGES 1600000
#define N_FEAT  16
#define HIDDEN  128
#define N_GRAPHS 512
#define HU2 (HIDDEN / 4)          // 32 uint2 (4 bf16) per node row
#define SCAN_B 1024
#define NB ((N_NODES + SCAN_B - 1) / SCAN_B)   // 98
#define TILE_M 128
#define GRID2 ((N_NODES + TILE_M - 1) / TILE_M)  // 782
#define PITCH 272                 // smem row pitch (bytes): conflict-free frag loads
#define SM_GEMM2 (2 * 128 * PITCH)  // 69632 dynamic smem

// ---- scratch ----
__device__ uint4  g_hb[N_NODES * 16];     // h*dinv, bf16 rows (gather in / gemm out)
__device__ uint4  g_outb[N_NODES * 16];   // relu(out+b), bf16 rows (gemm2 A / pool in)
__device__ uint4  g_xb[N_NODES * 2];      // x as bf16 rows (16 bf16 = 32B per node)
__device__ uint4  g_w2tb[128 * 16];       // W2^T as bf16 [n][k]
__device__ uint4  g_w1tb[128 * 2];        // W1^T as bf16 [n][k], k=16
__device__ float  g_dinv[N_NODES];
__device__ int    g_deg[N_NODES];
__device__ int    g_cursor[N_NODES];
__device__ int    g_row_start[N_NODES + 1];
__device__ int    g_blocksum[NB];
__device__ int    g_csr_src[N_EDGES];

__device__ __forceinline__ int idx_at(const int* __restrict__ p, int i, int is64) {
    return is64 ? p[2 * i] : p[i];
}

// Lane-parallel dtype detect: indices < 2^31, random — if int64, odd words all 0.
__device__ __forceinline__ int detect64(const int* __restrict__ p) {
    int lane = threadIdx.x & 31;
    int z = (p[2 * lane + 1] == 0);
    return __all_sync(0xffffffffu, z);
}

__device__ __forceinline__ uint32_t smem_u32(const void* p) {
    uint32_t a;
    asm("{ .reg .u64 t; cvta.to.shared.u64 t, %1; cvt.u32.u64 %0, t; }" : "=r"(a) : "l"(p));
    return a;
}

// ---------------------------------------------------------------------------
// x (fp32) -> g_xb (bf16). 8 values per thread. No dependencies.
__global__ void xcvt_kernel(const float* __restrict__ x) {
    int t = blockIdx.x * 256 + threadIdx.x;
    if (t >= N_NODES * 2) return;
    float4 lo4 = __ldg((const float4*)x + t * 2);
    float4 hi4 = __ldg((const float4*)x + t * 2 + 1);
    uint4 u;
    asm("cvt.rn.bf16x2.f32 %0, %1, %2;" : "=r"(u.x) : "f"(lo4.y), "f"(lo4.x));
    asm("cvt.rn.bf16x2.f32 %0, %1, %2;" : "=r"(u.y) : "f"(lo4.w), "f"(lo4.z));
    asm("cvt.rn.bf16x2.f32 %0, %1, %2;" : "=r"(u.z) : "f"(hi4.y), "f"(hi4.x));
    asm("cvt.rn.bf16x2.f32 %0, %1, %2;" : "=r"(u.w) : "f"(hi4.w), "f"(hi4.z));
    g_xb[t] = u;
}

// W1 -> w1tb[n][k] bf16 (transposed). 256 threads: n = t>>1, 8-k chunk = t&1.
__global__ void w1cvt_kernel(const float* __restrict__ W1) {
    int t = threadIdx.x;
    if (t >= 256) return;
    int n = t >> 1, ch = t & 1;
    int k0 = ch * 8;
    uint32_t w[4];
#pragma unroll
    for (int j = 0; j < 4; j++) {
        float lo = W1[(k0 + 2 * j) * HIDDEN + n];
        float hi = W1[(k0 + 2 * j + 1) * HIDDEN + n];
        asm("cvt.rn.bf16x2.f32 %0, %1, %2;" : "=r"(w[j]) : "f"(hi), "f"(lo));
    }
    g_w1tb[t] = make_uint4(w[0], w[1], w[2], w[3]);
}

// W2 -> w2tb[n][k] bf16 (transposed)
__global__ void w2cvt_kernel(const float* __restrict__ W2) {
    int t = blockIdx.x * 256 + threadIdx.x;
    if (t >= 128 * 16) return;
    int n = t >> 4, ch = t & 15;
    int k0 = ch * 8;
    uint32_t w[4];
#pragma unroll
    for (int j = 0; j < 4; j++) {
        float lo = W2[(k0 + 2 * j) * HIDDEN + n];
        float hi = W2[(k0 + 2 * j + 1) * HIDDEN + n];
        asm("cvt.rn.bf16x2.f32 %0, %1, %2;" : "=r"(w[j]) : "f"(hi), "f"(lo));
    }
    g_w2tb[t] = make_uint4(w[0], w[1], w[2], w[3]);
}

__global__ void deg_kernel(const int* __restrict__ ei_raw) {
    int is64 = detect64(ei_raw);
    int e = blockIdx.x * blockDim.x + threadIdx.x;
    if (e >= N_EDGES) return;
    const int* dst = ei_raw + (is64 ? 2 * N_EDGES : N_EDGES);
    atomicAdd(&g_deg[idx_at(dst, e, is64)], 1);
}

__global__ void dinv_kernel() {
    int i = blockIdx.x * blockDim.x + threadIdx.x;
    if (i < N_NODES) g_dinv[i] = rsqrtf((float)g_deg[i] + 1.0f);
}

__global__ void blocksum_kernel() {
    __shared__ int wsum[32];
    int b = blockIdx.x, tid = threadIdx.x;
    int i = b * SCAN_B + tid;
    int v = (i < N_NODES) ? g_deg[i] : 0;
#pragma unroll
    for (int off = 16; off; off >>= 1) v += __shfl_down_sync(0xffffffffu, v, off);
    if ((tid & 31) == 0) wsum[tid >> 5] = v;
    __syncthreads();
    if (tid < 32) {
        int s = (tid < SCAN_B / 32) ? wsum[tid] : 0;
#pragma unroll
        for (int off = 16; off; off >>= 1) s += __shfl_down_sync(0xffffffffu, s, off);
        if (tid == 0) g_blocksum[b] = s;
    }
}

// rowstart: hierarchical shfl scan (2 barriers) + inline prefix of blocksums
__global__ void rowstart_kernel() {
    __shared__ int wsum[32];
    __shared__ int s_pref;
    int b = blockIdx.x, tid = threadIdx.x;
    int lane = tid & 31, wrp = tid >> 5;

    if (tid < 32) {
        int sum = 0;
        for (int j = tid; j < b; j += 32) sum += g_blocksum[j];
#pragma unroll
        for (int off = 16; off; off >>= 1) sum += __shfl_down_sync(0xffffffffu, sum, off);
        if (tid == 0) s_pref = sum;
    }

    int i = b * SCAN_B + tid;
    int v = (i < N_NODES) ? g_deg[i] : 0;
    int sv = v;
#pragma unroll
    for (int off = 1; off < 32; off <<= 1) {
        int t = __shfl_up_sync(0xffffffffu, sv, off);
        if (lane >= off) sv += t;
    }
    if (lane == 31) wsum[wrp] = sv;
    __syncthreads();
    if (wrp == 0) {
        int s = wsum[lane];
#pragma unroll
        for (int off = 1; off < 32; off <<= 1) {
            int t = __shfl_up_sync(0xffffffffu, s, off);
            if (lane >= off) s += t;
        }
        wsum[lane] = s;
    }
    __syncthreads();
    int incl = sv + (wrp ? wsum[wrp - 1] : 0);
    int excl = incl - v + s_pref;
    if (i < N_NODES) g_row_start[i] = excl;
    if (i == N_NODES - 1) g_row_start[N_NODES] = excl + v;
}

__global__ void bin_kernel(const int* __restrict__ ei_raw) {
    int is64 = detect64(ei_raw);
    int e = blockIdx.x * blockDim.x + threadIdx.x;
    if (e >= N_EDGES) return;
    const int* src = ei_raw;
    const int* dst = ei_raw + (is64 ? 2 * N_EDGES : N_EDGES);
    int d = idx_at(dst, e, is64);
    int pos = atomicAdd(&g_cursor[d], 1);
    g_csr_src[g_row_start[d] + pos] = idx_at(src, e, is64);
}

// ---------------------------------------------------------------------------
// Layer 1 GEMM via HMMA, zero smem: g_hb = bf16( (x_bf16 @ W1) * dinv ).
// CTA: 128 rows; warp = m16 x n128, single k-step (K=16). Frags via direct LDG.
__global__ __launch_bounds__(256) void gemm1_hmma_kernel() {
    int tid = threadIdx.x, wid = tid >> 5, lane = tid & 31;
    int row0 = blockIdx.x * TILE_M;
    int r = lane >> 2;
    int kc = (lane & 3) * 4;     // byte offset of k-pair

    // B frags from g_w1tb (4KB, L1-resident): 16 n-frags x {b0,b1}
    const uint8_t* w1b = (const uint8_t*)g_w1tb;
    uint32_t b0[16], b1[16];
#pragma unroll
    for (int f = 0; f < 16; f++) {
        const uint8_t* p = w1b + (f * 8 + r) * 32 + kc;
        b0[f] = *(const uint32_t*)p;
        b1[f] = *(const uint32_t*)(p + 16);
    }

    // A frags from g_xb (32B per row)
    int rlo = row0 + wid * 16 + r;
    int rhi = rlo + 8;
    const uint8_t* xb = (const uint8_t*)g_xb;
    bool vlo = rlo < N_NODES, vhi = rhi < N_NODES;
    uint32_t a0 = vlo ? *(const uint32_t*)(xb + rlo * 32 + kc) : 0u;
    uint32_t a2 = vlo ? *(const uint32_t*)(xb + rlo * 32 + kc + 16) : 0u;
    uint32_t a1 = vhi ? *(const uint32_t*)(xb + rhi * 32 + kc) : 0u;
    uint32_t a3 = vhi ? *(const uint32_t*)(xb + rhi * 32 + kc + 16) : 0u;

    float dlo = vlo ? g_dinv[rlo] : 0.f;
    float dhi = vhi ? g_dinv[rhi] : 0.f;
    uint32_t* ghw = (uint32_t*)g_hb;
    int wcol = lane & 3;

#pragma unroll
    for (int f = 0; f < 16; f++) {
        float c0 = 0.f, c1 = 0.f, c2 = 0.f, c3 = 0.f;
        asm volatile(
            "mma.sync.aligned.m16n8k16.row.col.f32.bf16.bf16.f32 "
            "{%0,%1,%2,%3},{%4,%5,%6,%7},{%8,%9},{%0,%1,%2,%3};"
            : "+f"(c0), "+f"(c1), "+f"(c2), "+f"(c3)
            : "r"(a0), "r"(a1), "r"(a2), "r"(a3), "r"(b0[f]), "r"(b1[f]));
        uint32_t plo, phi;
        asm("cvt.rn.bf16x2.f32 %0, %1, %2;" : "=r"(plo) : "f"(c1 * dlo), "f"(c0 * dlo));
        asm("cvt.rn.bf16x2.f32 %0, %1, %2;" : "=r"(phi) : "f"(c3 * dhi), "f"(c2 * dhi));
        if (vlo) ghw[rlo * 64 + f * 4 + wcol] = plo;
        if (vhi) ghw[rhi * 64 + f * 4 + wcol] = phi;
    }
}

// ---------------------------------------------------------------------------
// CSR gather: v = dinv[d]*(h_pre[d] + Σ_s h_pre[s]) + bias;  g_outb = bf16(relu(v))
// Warp per dst node; half-warp per edge, uint4 (8 bf16) per lane.
__global__ void gather_kernel(const float* __restrict__ bias) {
    int w = (blockIdx.x * blockDim.x + threadIdx.x) >> 5;
    int lane = threadIdx.x & 31;
    if (w >= N_NODES) return;

    int beg = g_row_start[w];
    int end = g_row_start[w + 1];
    int half = lane >> 4;
    int l16 = lane & 15;

    float a0 = 0.f, a1 = 0.f, a2 = 0.f, a3 = 0.f;
    float a4 = 0.f, a5 = 0.f, a6 = 0.f, a7 = 0.f;

    int i = beg;
    for (; i + 1 < end; i += 2) {
        int s = g_csr_src[i + half];
        uint4 v = g_hb[s * 16 + l16];
        float2 f0 = __bfloat1622float2(*(__nv_bfloat162*)&v.x);
        float2 f1 = __bfloat1622float2(*(__nv_bfloat162*)&v.y);
        float2 f2 = __bfloat1622float2(*(__nv_bfloat162*)&v.z);
        float2 f3 = __bfloat1622float2(*(__nv_bfloat162*)&v.w);
        a0 += f0.x; a1 += f0.y; a2 += f1.x; a3 += f1.y;
        a4 += f2.x; a5 += f2.y; a6 += f3.x; a7 += f3.y;
    }
    if (i < end && half == 0) {
        int s = g_csr_src[i];
        uint4 v = g_hb[s * 16 + l16];
        float2 f0 = __bfloat1622float2(*(__nv_bfloat162*)&v.x);
        float2 f1 = __bfloat1622float2(*(__nv_bfloat162*)&v.y);
        float2 f2 = __bfloat1622float2(*(__nv_bfloat162*)&v.z);
        float2 f3 = __bfloat1622float2(*(__nv_bfloat162*)&v.w);
        a0 += f0.x; a1 += f0.y; a2 += f1.x; a3 += f1.y;
        a4 += f2.x; a5 += f2.y; a6 += f3.x; a7 += f3.y;
    }

    a0 += __shfl_xor_sync(0xffffffffu, a0, 16);
    a1 += __shfl_xor_sync(0xffffffffu, a1, 16);
    a2 += __shfl_xor_sync(0xffffffffu, a2, 16);
    a3 += __shfl_xor_sync(0xffffffffu, a3, 16);
    a4 += __shfl_xor_sync(0xffffffffu, a4, 16);
    a5 += __shfl_xor_sync(0xffffffffu, a5, 16);
    a6 += __shfl_xor_sync(0xffffffffu, a6, 16);
    a7 += __shfl_xor_sync(0xffffffffu, a7, 16);

    if (half == 0) {
        uint4 v = g_hb[w * 16 + l16];
        float2 f0 = __bfloat1622float2(*(__nv_bfloat162*)&v.x);
        float2 f1 = __bfloat1622float2(*(__nv_bfloat162*)&v.y);
        float2 f2 = __bfloat1622float2(*(__nv_bfloat162*)&v.z);
        float2 f3 = __bfloat1622float2(*(__nv_bfloat162*)&v.w);
        a0 += f0.x; a1 += f0.y; a2 += f1.x; a3 += f1.y;
        a4 += f2.x; a5 += f2.y; a6 += f3.x; a7 += f3.y;

        float invd = g_dinv[w];
        float4 b0 = ((const float4*)bias)[l16 * 2];
        float4 b1 = ((const float4*)bias)[l16 * 2 + 1];
        float v0 = fmaxf(a0 * invd + b0.x, 0.f);
        float v1 = fmaxf(a1 * invd + b0.y, 0.f);
        float v2 = fmaxf(a2 * invd + b0.z, 0.f);
        float v3 = fmaxf(a3 * invd + b0.w, 0.f);
        float v4 = fmaxf(a4 * invd + b1.x, 0.f);
        float v5 = fmaxf(a5 * invd + b1.y, 0.f);
        float v6 = fmaxf(a6 * invd + b1.z, 0.f);
        float v7 = fmaxf(a7 * invd + b1.w, 0.f);
        uint4 o;
        asm("cvt.rn.bf16x2.f32 %0, %1, %2;" : "=r"(o.x) : "f"(v1), "f"(v0));
        asm("cvt.rn.bf16x2.f32 %0, %1, %2;" : "=r"(o.y) : "f"(v3), "f"(v2));
        asm("cvt.rn.bf16x2.f32 %0, %1, %2;" : "=r"(o.z) : "f"(v5), "f"(v4));
        asm("cvt.rn.bf16x2.f32 %0, %1, %2;" : "=r"(o.w) : "f"(v7), "f"(v6));
        g_outb[w * 16 + l16] = o;
    }
}

// ---------------------------------------------------------------------------
// Layer 2 GEMM via mma.sync (HMMA): g_hb = bf16((g_outb @ W2) * dinv)
__global__ __launch_bounds__(256) void gemm2_hmma_kernel() {
    extern __shared__ __align__(16) uint8_t smem[];
    uint8_t* sA = smem;
    uint8_t* sB = smem + 128 * PITCH;

    int tid = threadIdx.x, wid = tid >> 5, lane = tid & 31;
    int row0 = blockIdx.x * TILE_M;

    const uint4 zero4 = make_uint4(0, 0, 0, 0);
    for (int g = tid; g < 2048; g += 256) {
        int row = g >> 4, ch = g & 15;
        uint4 va = (row0 + row < N_NODES) ? g_outb[(row0 + row) * 16 + ch] : zero4;
        *(uint4*)(sA + row * PITCH + ch * 16) = va;
        *(uint4*)(sB + row * PITCH + ch * 16) = g_w2tb[g];
    }
    __syncthreads();

    float acc[16][4];
#pragma unroll
    for (int f = 0; f < 16; f++)
#pragma unroll
        for (int j = 0; j < 4; j++) acc[f][j] = 0.f;

    int r = lane >> 2;
    int kc2 = (lane & 3) * 4;
    uint32_t aAddr = smem_u32(sA) + (wid * 16 + r) * PITCH + kc2;
    uint32_t bAddr = smem_u32(sB) + r * PITCH + kc2;

#pragma unroll
    for (int ks = 0; ks < 8; ks++) {
        uint32_t a0, a1, a2, a3;
        uint32_t ka = aAddr + ks * 32;
        asm volatile("ld.shared.b32 %0,[%1];" : "=r"(a0) : "r"(ka));
        asm volatile("ld.shared.b32 %0,[%1];" : "=r"(a1) : "r"(ka + 8 * PITCH));
        asm volatile("ld.shared.b32 %0,[%1];" : "=r"(a2) : "r"(ka + 16));
        asm volatile("ld.shared.b32 %0,[%1];" : "=r"(a3) : "r"(ka + 8 * PITCH + 16));
#pragma unroll
        for (int f = 0; f < 16; f++) {
            uint32_t b0, b1;
            uint32_t kb = bAddr + ks * 32 + f * 8 * PITCH;
            asm volatile("ld.shared.b32 %0,[%1];" : "=r"(b0) : "r"(kb));
            asm volatile("ld.shared.b32 %0,[%1];" : "=r"(b1) : "r"(kb + 16));
            asm volatile(
                "mma.sync.aligned.m16n8k16.row.col.f32.bf16.bf16.f32 "
                "{%0,%1,%2,%3},{%4,%5,%6,%7},{%8,%9},{%0,%1,%2,%3};"
                : "+f"(acc[f][0]), "+f"(acc[f][1]), "+f"(acc[f][2]), "+f"(acc[f][3])
                : "r"(a0), "r"(a1), "r"(a2), "r"(a3), "r"(b0), "r"(b1));
        }
    }

    int rlo = row0 + wid * 16 + r;
    int rhi = rlo + 8;
    float dlo = (rlo < N_NODES) ? g_dinv[rlo] : 0.f;
    float dhi = (rhi < N_NODES) ? g_dinv[rhi] : 0.f;
    uint32_t* ghw = (uint32_t*)g_hb;
    int wcol = (lane & 3);
#pragma unroll
    for (int f = 0; f < 16; f++) {
        uint32_t plo, phi;
        asm("cvt.rn.bf16x2.f32 %0, %1, %2;" : "=r"(plo)
            : "f"(acc[f][1] * dlo), "f"(acc[f][0] * dlo));
        asm("cvt.rn.bf16x2.f32 %0, %1, %2;" : "=r"(phi)
            : "f"(acc[f][3] * dhi), "f"(acc[f][2] * dhi));
        if (rlo < N_NODES) ghw[rlo * 64 + f * 4 + wcol] = plo;
        if (rhi < N_NODES) ghw[rhi * 64 + f * 4 + wcol] = phi;
    }
}

// ---------------------------------------------------------------------------
// Pool + head fused: block per graph (batch sorted). Input g_outb (bf16).
__global__ void pool_head_kernel(const int* __restrict__ batch_raw,
                                 const int* __restrict__ ei_raw,
                                 const float* __restrict__ Wl,
                                 const float* __restrict__ bl,
                                 float* __restrict__ out) {
    int g = blockIdx.x;
    int tid = threadIdx.x;
    int is64 = detect64(ei_raw);

    int lo = 0, hi = N_NODES;
    while (lo < hi) {
        int mid = (lo + hi) >> 1;
        if (idx_at(batch_raw, mid, is64) < g) lo = mid + 1; else hi = mid;
    }
    int beg = lo;
    hi = N_NODES;
    while (lo < hi) {
        int mid = (lo + hi) >> 1;
        if (idx_at(batch_raw, mid, is64) < g + 1) lo = mid + 1; else hi = mid;
    }
    int end = lo;

    const __nv_bfloat16* outb = (const __nv_bfloat16*)g_outb;
    float acc = 0.f;
    for (int n = beg; n < end; n++)
        acc += __bfloat162float(outb[n * HIDDEN + tid]);

    float v = acc * __ldg(Wl + tid);
    __shared__ float wsum[4];
#pragma unroll
    for (int off = 16; off; off >>= 1) v += __shfl_down_sync(0xffffffffu, v, off);
    if ((tid & 31) == 0) wsum[tid >> 5] = v;
    __syncthreads();
    if (tid == 0) {
        float tot = wsum[0] + wsum[1] + wsum[2] + wsum[3];
        float cnt = fmaxf((float)(end - beg), 1.0f);
        out[g] = tot / cnt + __ldg(bl);
    }
}

// ---------------------------------------------------------------------------
extern "C" void kernel_launch(void* const* d_in, const int* in_sizes, int n_in,
                              void* d_out, int out_size) {
    const float* x = (const float*)d_in[0];
    const int* ei_raw = (const int*)d_in[1];
    const int* batch_raw = (const int*)d_in[2];
    const float* W1 = (const float*)d_in[3];
    const float* b1 = (const float*)d_in[4];
    const float* W2 = (const float*)d_in[5];
    const float* b2 = (const float*)d_in[6];
    const float* Wl = (const float*)d_in[7];
    const float* bl = (const float*)d_in[8];
    float* out = (float*)d_out;

    static cudaStream_t s1 = nullptr;
    static cudaEvent_t evF = nullptr, evD = nullptr, evJ = nullptr;
    if (!s1) {
        cudaStreamCreate(&s1);
        cudaEventCreateWithFlags(&evF, cudaEventDisableTiming);
        cudaEventCreateWithFlags(&evD, cudaEventDisableTiming);
        cudaEventCreateWithFlags(&evJ, cudaEventDisableTiming);
        cudaFuncSetAttribute(gemm2_hmma_kernel,
                             cudaFuncAttributeMaxDynamicSharedMemorySize, SM_GEMM2);
    }

    void *p_deg = nullptr, *p_cur = nullptr;
    cudaGetSymbolAddress(&p_deg, g_deg);
    cudaGetSymbolAddress(&p_cur, g_cursor);
    cudaMemsetAsync(p_deg, 0, N_NODES * sizeof(int));
    cudaMemsetAsync(p_cur, 0, N_NODES * sizeof(int));

    // Fork: side stream converts weights and x (no deps)
    cudaEventRecord(evF, 0);
    cudaStreamWaitEvent(s1, evF, 0);
    w1cvt_kernel<<<1, 256, 0, s1>>>(W1);
    w2cvt_kernel<<<8, 256, 0, s1>>>(W2);
    xcvt_kernel<<<(N_NODES * 2 + 255) / 256, 256, 0, s1>>>(x);

    // Main: degree -> dinv
    deg_kernel<<<(N_EDGES + 255) / 256, 256>>>(ei_raw);
    dinv_kernel<<<(N_NODES + 255) / 256, 256>>>();
    cudaEventRecord(evD, 0);

    // Side: gemm1 (needs dinv + xb + w1tb) overlapped with scan+bin on main
    cudaStreamWaitEvent(s1, evD, 0);
    gemm1_hmma_kernel<<<GRID2, 256, 0, s1>>>();
    cudaEventRecord(evJ, s1);

    blocksum_kernel<<<NB, SCAN_B>>>();
    rowstart_kernel<<<NB, SCAN_B>>>();
    bin_kernel<<<(N_EDGES + 255) / 256, 256>>>(ei_raw);

    // Join, then the serial back half
    cudaStreamWaitEvent(0, evJ, 0);
    gather_kernel<<<(N_NODES + 7) / 8, 256>>>(b1);
    gemm2_hmma_kernel<<<GRID2, 256, SM_GEMM2>>>();
    gather_kernel<<<(N_NODES + 7) / 8, 256>>>(b2);
    pool_head_kernel<<<N_GRAPHS, 128>>>(batch_raw, ei_raw, Wl, bl, out);
}